// round 9
// baseline (speedup 1.0000x reference)
#include <cuda_runtime.h>
#include <cstdint>

#define MAX_NODES 50000
#define LAT       100
#define NGRAPH    256
#define H2        200
#define NCLASS    55
#define MAX_EDGES 800000
#define KMAX      512

typedef unsigned long long u64;

// ---------------- scratch (device globals) ---------------------------------
__device__ __align__(16) float g_bufA[MAX_NODES * LAT];   // x0 * inv_out
__device__ __align__(16) float g_bufB[MAX_NODES * LAT];   // P(x0) * inv_in * inv_out
__device__ __align__(16) float g_inv_out[MAX_NODES];
__device__ __align__(16) float g_inv_in[MAX_NODES];
__device__ __align__(16) float g_s1[MAX_NODES];           // inv_in * inv_out
__device__ __align__(16) int   g_off[MAX_NODES + 16];
__device__ __align__(16) int   g_cur[MAX_NODES];
__device__ __align__(16) int   g_csr[MAX_EDGES];
__device__ __align__(16) int   g_bsum[80];
__device__ __align__(16) int   g_bpre[80];
__device__ __align__(16) float g_Wt[LAT * KMAX];          // W_ext transposed [c][k]
__device__ __align__(16) float g_W12[LAT * H2];           // W1 @ W2
__device__ __align__(16) float g_Wfin[LAT * NCLASS];      // W1 @ W2 @ Wc
__device__ __align__(16) float g_v1[64];                  // b1 @ W2 @ Wc
__device__ __align__(16) float g_c0[64];                  // b2 @ Wc + bc

// packed zero region: out_deg(f32) | deg_in(i32) | poolX | poolD | cnt
#define ZR_OUTDEG 0
#define ZR_DEGIN  50000
#define ZR_POOLX  100000
#define ZR_POOLD  125600
#define ZR_CNT    125856
#define ZR_TOTAL  126112
__device__ __align__(16) float g_zregion[ZR_TOTAL];

// ---------------- f32x2 packed math helpers --------------------------------
__device__ __forceinline__ void ffma2(u64& d, u64 a, u64 b) {
    asm("fma.rn.f32x2 %0, %1, %2, %0;" : "+l"(d) : "l"(a), "l"(b));
}
__device__ __forceinline__ float2 unpack2(u64 v) {
    float2 f; asm("mov.b64 {%0, %1}, %2;" : "=f"(f.x), "=f"(f.y) : "l"(v)); return f;
}

// ---------------- cp.async helpers -----------------------------------------
__device__ __forceinline__ void cp_async16(uint32_t saddr, const void* gptr) {
    asm volatile("cp.async.ca.shared.global [%0], [%1], 16;"
                 :: "r"(saddr), "l"(gptr));
}
__device__ __forceinline__ void cp_commit() {
    asm volatile("cp.async.commit_group;");
}
__device__ __forceinline__ void cp_wait_all() {
    asm volatile("cp.async.wait_group 0;");
}

// ---------------- prep: zero scratch + transpose W_ext ----------------------
__global__ void prep_kernel(const float* __restrict__ W_ext, int K) {
    int i = blockIdx.x * blockDim.x + threadIdx.x;
    int stride = gridDim.x * blockDim.x;
    float4* z = (float4*)g_zregion;
    float4 zv = make_float4(0.f, 0.f, 0.f, 0.f);
    for (int t = i; t < ZR_TOTAL / 4; t += stride) z[t] = zv;
    int tot = LAT * K;
    for (int t = i; t < tot; t += stride) {
        int c = t / K, k = t - c * K;
        g_Wt[t] = W_ext[(size_t)k * LAT + c];
    }
}

__global__ void degree_kernel(const int* __restrict__ src, const int* __restrict__ dst, int E) {
    float* out_deg = g_zregion + ZR_OUTDEG;
    int*   deg_in  = (int*)(g_zregion + ZR_DEGIN);
    int i = blockIdx.x * blockDim.x + threadIdx.x;
    if (i < E) {
        atomicAdd(&out_deg[src[i]], 1.0f);
        atomicAdd(&deg_in[dst[i]], 1);
    }
}

// scanA: per-chunk reduce of deg_in; also rsqrt factors + per-graph counts
__global__ void scanA_kernel(const int* __restrict__ gid, int n) {
    __shared__ int wsum[32];
    const float* out_deg = g_zregion + ZR_OUTDEG;
    const int*   deg_in  = (const int*)(g_zregion + ZR_DEGIN);
    float* cnt = g_zregion + ZR_CNT;
    int tid = threadIdx.x, lane = tid & 31, warp = tid >> 5;
    int i = blockIdx.x * 1024 + tid;
    int v = 0;
    if (i < n) {
        v = deg_in[i];
        float ii = rsqrtf(fmaxf((float)v, 1.0f));
        float io = rsqrtf(fmaxf(out_deg[i], 1.0f));
        g_inv_in[i]  = ii;
        g_inv_out[i] = io;
        g_s1[i]      = ii * io;
        atomicAdd(&cnt[gid[i]], 1.0f);
    }
    int s = v;
#pragma unroll
    for (int d = 16; d > 0; d >>= 1) s += __shfl_down_sync(0xffffffffu, s, d);
    if (lane == 0) wsum[warp] = s;
    __syncthreads();
    if (warp == 0) {
        int t = (lane < 32) ? wsum[lane] : 0;
#pragma unroll
        for (int d = 16; d > 0; d >>= 1) t += __shfl_down_sync(0xffffffffu, t, d);
        if (lane == 0) g_bsum[blockIdx.x] = t;
    }
}

__global__ void scanB_kernel(int nb, int n) {
    __shared__ int s[80];
    int tid = threadIdx.x;
    if (tid < nb) s[tid] = g_bsum[tid];
    __syncthreads();
    if (tid == 0) {
        int run = 0;
        for (int b = 0; b < nb; b++) { int t = s[b]; s[b] = run; run += t; }
        g_off[n] = run;
    }
    __syncthreads();
    if (tid < nb) g_bpre[tid] = s[tid];
}

__global__ void scanC_kernel(int n) {
    __shared__ int wsum[32];
    const int* deg_in = (const int*)(g_zregion + ZR_DEGIN);
    int tid = threadIdx.x, lane = tid & 31, warp = tid >> 5;
    int i = blockIdx.x * 1024 + tid;
    int v = (i < n) ? deg_in[i] : 0;
    int s = v;
#pragma unroll
    for (int d = 1; d < 32; d <<= 1) {
        int t = __shfl_up_sync(0xffffffffu, s, d);
        if (lane >= d) s += t;
    }
    if (lane == 31) wsum[warp] = s;
    __syncthreads();
    if (warp == 0) {
        int ws = wsum[lane];
#pragma unroll
        for (int d = 1; d < 32; d <<= 1) {
            int t = __shfl_up_sync(0xffffffffu, ws, d);
            if (lane >= d) ws += t;
        }
        wsum[lane] = ws;
    }
    __syncthreads();
    int wpre = (warp > 0) ? wsum[warp - 1] : 0;
    int excl = s - v + wpre + g_bpre[blockIdx.x];
    if (i < n) { g_off[i] = excl; g_cur[i] = excl; }
}

__global__ void scatter_kernel(const int* __restrict__ src, const int* __restrict__ dst, int E) {
    int i = blockIdx.x * blockDim.x + threadIdx.x;
    if (i < E) {
        int p = atomicAdd(&g_cur[dst[i]], 1);
        g_csr[p] = src[i];
    }
}

// ---------------- CSR propagation -----------------------------------------
template <bool POOL>
__global__ void prop_csr_kernel(const float4* __restrict__ xs,
                                float4* __restrict__ agg,
                                const float* __restrict__ scale,
                                const int* __restrict__ gid, int n) {
    int node = (blockIdx.x * blockDim.x + threadIdx.x) >> 5;
    int lane = threadIdx.x & 31;
    if (node >= n) return;
    int b = g_off[node], e = g_off[node + 1];
    bool act = lane < 25;
    bool dt  = (!POOL) && (lane == 25);
    float4 a0 = make_float4(0.f, 0.f, 0.f, 0.f);
    float4 a1 = a0, a2 = a0, a3 = a0;
    float sd = 0.f;
    unsigned base = (unsigned)lane;
    int k = b;
    for (; k + 4 <= e; k += 4) {
        int s0 = g_csr[k], s1 = g_csr[k + 1], s2 = g_csr[k + 2], s3 = g_csr[k + 3];
        if (act) {
            float4 v0 = xs[(unsigned)s0 * 25u + base];
            float4 v1 = xs[(unsigned)s1 * 25u + base];
            float4 v2 = xs[(unsigned)s2 * 25u + base];
            float4 v3 = xs[(unsigned)s3 * 25u + base];
            a0.x += v0.x; a0.y += v0.y; a0.z += v0.z; a0.w += v0.w;
            a1.x += v1.x; a1.y += v1.y; a1.z += v1.z; a1.w += v1.w;
            a2.x += v2.x; a2.y += v2.y; a2.z += v2.z; a2.w += v2.w;
            a3.x += v3.x; a3.y += v3.y; a3.z += v3.z; a3.w += v3.w;
        } else if (dt) {
            sd += g_inv_out[s0] + g_inv_out[s1] + g_inv_out[s2] + g_inv_out[s3];
        }
    }
    for (; k < e; k++) {
        int s0 = g_csr[k];
        if (act) {
            float4 v0 = xs[(unsigned)s0 * 25u + base];
            a0.x += v0.x; a0.y += v0.y; a0.z += v0.z; a0.w += v0.w;
        } else if (dt) {
            sd += g_inv_out[s0];
        }
    }
    if (act) {
        float sc = scale[node];
        float x = (a0.x + a1.x + a2.x + a3.x) * sc;
        float y = (a0.y + a1.y + a2.y + a3.y) * sc;
        float z = (a0.z + a1.z + a2.z + a3.z) * sc;
        float w = (a0.w + a1.w + a2.w + a3.w) * sc;
        if (!POOL) {
            agg[(unsigned)node * 25u + base] = make_float4(x, y, z, w);
        } else {
            float* poolX = g_zregion + ZR_POOLX;
            float* p = poolX + (unsigned)gid[node] * 100u + base * 4u;
            asm volatile("red.global.add.v4.f32 [%0], {%1,%2,%3,%4};"
                         :: "l"(p), "f"(x), "f"(y), "f"(z), "f"(w)
                         : "memory");
        }
    } else if (dt) {
        float* poolD = g_zregion + ZR_POOLD;
        atomicAdd(&poolD[gid[node]], sd * g_inv_in[node]);
    }
}

// ---------------- GEMM0: C = (A @ W + b) .* sout ---------------------------
// v4: dot-packed f32x2 over K-pairs. Both operands K-contiguous -> both
// staged via cp.async, NO transpose, NO staging STS. TM=80, 256 threads,
// 250 workers x (8 rows x 4 cols, cols strided tx+25j). W smem pitch 36
// words makes the strided LDS.128 conflict-free (lane stride 144B).
#define TM 80
#define KC 32
#define APITCH 32
#define WPITCH 36
#define ABUF (TM * APITCH)          // words
#define WBUF (LAT * WPITCH)         // words
#define GSMEM ((2 * ABUF + 2 * WBUF) * 4)
__global__ void __launch_bounds__(256, 2) gemm0_kernel(
        const float* __restrict__ A,
        const float* __restrict__ Wt,    // [LAT][K] transposed weights
        const float* __restrict__ bias,
        const float* __restrict__ sout,
        float* __restrict__ C, int M, int K) {
    extern __shared__ float sm[];
    float* AsB = sm;                 // [2][TM][APITCH]
    float* WsB = sm + 2 * ABUF;      // [2][LAT][WPITCH]
    uint32_t abase = (uint32_t)__cvta_generic_to_shared(AsB);
    uint32_t wbase = (uint32_t)__cvta_generic_to_shared(WsB);

    int tid = threadIdx.x;
    int m0 = blockIdx.x * TM;
    bool worker = tid < 250;
    int ty = tid / 25;               // 0..9 for workers
    int tx = tid - ty * 25;          // 0..24
    int r0 = ty * 8;

    u64 acc[8][4];
#pragma unroll
    for (int r = 0; r < 8; r++)
#pragma unroll
        for (int j = 0; j < 4; j++) acc[r][j] = 0ull;

    int nk = (K + KC - 1) / KC;

    auto loadA = [&](int k0, int buf) {
#pragma unroll
        for (int s = 0; s < 3; s++) {
            int idx = tid + s * 256;
            if (idx < TM * (KC / 4)) {
                int row = idx >> 3, q = idx & 7;
                int gr = m0 + row; if (gr >= M) gr = M - 1;
                int gk = k0 + q * 4;
                uint32_t dst = abase + (buf * ABUF + row * APITCH + q * 4) * 4;
                if (gk + 3 < K) {
                    cp_async16(dst, &A[(size_t)gr * K + gk]);
                } else {
                    float4 v;
                    v.x = (gk     < K) ? A[(size_t)gr * K + gk]     : 0.f;
                    v.y = (gk + 1 < K) ? A[(size_t)gr * K + gk + 1] : 0.f;
                    v.z = (gk + 2 < K) ? A[(size_t)gr * K + gk + 2] : 0.f;
                    v.w = (gk + 3 < K) ? A[(size_t)gr * K + gk + 3] : 0.f;
                    *(float4*)&AsB[buf * ABUF + row * APITCH + q * 4] = v;
                }
            }
        }
    };
    auto loadW = [&](int k0, int buf) {
#pragma unroll
        for (int s = 0; s < 4; s++) {
            int idx = tid + s * 256;
            if (idx < LAT * (KC / 4)) {
                int c = idx >> 3, q = idx & 7;
                int gk = k0 + q * 4;
                uint32_t dst = wbase + (buf * WBUF + c * WPITCH + q * 4) * 4;
                if (gk + 3 < K) {
                    cp_async16(dst, &Wt[(size_t)c * K + gk]);
                } else {
                    float4 v;
                    v.x = (gk     < K) ? Wt[(size_t)c * K + gk]     : 0.f;
                    v.y = (gk + 1 < K) ? Wt[(size_t)c * K + gk + 1] : 0.f;
                    v.z = (gk + 2 < K) ? Wt[(size_t)c * K + gk + 2] : 0.f;
                    v.w = (gk + 3 < K) ? Wt[(size_t)c * K + gk + 3] : 0.f;
                    *(float4*)&WsB[buf * WBUF + c * WPITCH + q * 4] = v;
                }
            }
        }
    };

    // prologue
    loadA(0, 0);
    loadW(0, 0);
    cp_commit();
    cp_wait_all();
    __syncthreads();

    for (int ch = 0; ch < nk; ch++) {
        int buf = ch & 1;
        if (ch + 1 < nk) {
            loadA((ch + 1) * KC, buf ^ 1);
            loadW((ch + 1) * KC, buf ^ 1);
            cp_commit();
        }
        if (worker) {
            const float* Ab = AsB + buf * ABUF + r0 * APITCH;
            const float* Wb = WsB + buf * WBUF + tx * WPITCH;
#pragma unroll
            for (int k4 = 0; k4 < KC / 4; k4++) {
                ulonglong2 w0 = *(const ulonglong2*)(Wb + k4 * 4);
                ulonglong2 w1 = *(const ulonglong2*)(Wb + 25 * WPITCH + k4 * 4);
                ulonglong2 w2 = *(const ulonglong2*)(Wb + 50 * WPITCH + k4 * 4);
                ulonglong2 w3 = *(const ulonglong2*)(Wb + 75 * WPITCH + k4 * 4);
#pragma unroll
                for (int r = 0; r < 8; r++) {
                    ulonglong2 av = *(const ulonglong2*)(Ab + r * APITCH + k4 * 4);
                    ffma2(acc[r][0], av.x, w0.x); ffma2(acc[r][0], av.y, w0.y);
                    ffma2(acc[r][1], av.x, w1.x); ffma2(acc[r][1], av.y, w1.y);
                    ffma2(acc[r][2], av.x, w2.x); ffma2(acc[r][2], av.y, w2.y);
                    ffma2(acc[r][3], av.x, w3.x); ffma2(acc[r][3], av.y, w3.y);
                }
            }
        }
        if (ch + 1 < nk) {
            cp_wait_all();
            __syncthreads();
        }
    }

    if (worker) {
        float b0 = bias[tx], b1 = bias[tx + 25], b2 = bias[tx + 50], b3 = bias[tx + 75];
#pragma unroll
        for (int r = 0; r < 8; r++) {
            int row = m0 + r0 + r;
            if (row < M) {
                float so = sout[row];
                float2 p0 = unpack2(acc[r][0]);
                float2 p1 = unpack2(acc[r][1]);
                float2 p2 = unpack2(acc[r][2]);
                float2 p3 = unpack2(acc[r][3]);
                float* Cr = C + (size_t)row * LAT;
                Cr[tx]      = (p0.x + p0.y + b0) * so;
                Cr[tx + 25] = (p1.x + p1.y + b1) * so;
                Cr[tx + 50] = (p2.x + p2.y + b2) * so;
                Cr[tx + 75] = (p3.x + p3.y + b3) * so;
            }
        }
    }
}

// ---------------- weight folding (all tiny) --------------------------------
__global__ void wprec1_kernel(const float* __restrict__ W1, const float* __restrict__ W2) {
    int idx = blockIdx.x * blockDim.x + threadIdx.x;
    if (idx >= LAT * H2) return;
    int i = idx / H2, j = idx % H2;
    float acc = 0.f;
    for (int k = 0; k < LAT; k++) acc += W1[i * LAT + k] * W2[k * H2 + j];
    g_W12[idx] = acc;
}
__global__ void wprec2_kernel(const float* __restrict__ Wc) {
    int idx = blockIdx.x * blockDim.x + threadIdx.x;
    if (idx >= LAT * NCLASS) return;
    int i = idx / NCLASS, j = idx % NCLASS;
    float acc = 0.f;
    for (int k = 0; k < H2; k++) acc += g_W12[i * H2 + k] * Wc[k * NCLASS + j];
    g_Wfin[idx] = acc;
}
__global__ void wprec3_kernel(const float* __restrict__ b1, const float* __restrict__ W2,
                              const float* __restrict__ b2, const float* __restrict__ Wc,
                              const float* __restrict__ bc) {
    __shared__ float bw2[H2];
    int tid = threadIdx.x;
    for (int k = tid; k < H2; k += blockDim.x) {
        float acc = 0.f;
        for (int j = 0; j < LAT; j++) acc += b1[j] * W2[j * H2 + k];
        bw2[k] = acc;
    }
    __syncthreads();
    if (tid < NCLASS) {
        float v = 0.f, c = 0.f;
        for (int k = 0; k < H2; k++) {
            v += bw2[k] * Wc[k * NCLASS + tid];
            c += b2[k] * Wc[k * NCLASS + tid];
        }
        g_v1[tid] = v;
        g_c0[tid] = c + bc[tid];
    }
}

// ---------------- final: out[g,c] ------------------------------------------
__global__ void final_kernel(float* __restrict__ out) {
    __shared__ float px[LAT];
    __shared__ float spd;
    const float* poolX = g_zregion + ZR_POOLX;
    const float* poolD = g_zregion + ZR_POOLD;
    const float* cnt   = g_zregion + ZR_CNT;
    int g = blockIdx.x, tid = threadIdx.x;
    float invc = 1.0f / fmaxf(cnt[g], 1.0f);
    for (int i = tid; i < LAT; i += blockDim.x) px[i] = poolX[g * LAT + i] * invc;
    if (tid == 0) spd = poolD[g] * invc;
    __syncthreads();
    if (tid < NCLASS) {
        float acc = g_c0[tid] + spd * g_v1[tid];
        for (int k = 0; k < LAT; k++) acc += px[k] * g_Wfin[k * NCLASS + tid];
        out[g * NCLASS + tid] = acc;
    }
}

// ---------------- launch ---------------------------------------------------
extern "C" void kernel_launch(void* const* d_in, const int* in_sizes, int n_in,
                              void* d_out, int out_size) {
    const float* fsnet = (const float*)d_in[0];
    const int*   src   = (const int*)d_in[1];
    const int*   dst   = (const int*)d_in[2];
    const int*   gid   = (const int*)d_in[3];
    const float* W_ext = (const float*)d_in[4];
    const float* b_ext = (const float*)d_in[5];
    const float* W1    = (const float*)d_in[6];
    const float* b1    = (const float*)d_in[7];
    const float* W2    = (const float*)d_in[8];
    const float* b2    = (const float*)d_in[9];
    const float* Wc    = (const float*)d_in[10];
    const float* bc    = (const float*)d_in[11];
    float* out = (float*)d_out;

    int n   = in_sizes[3];
    int E   = in_sizes[1];
    int RAW = in_sizes[4] / LAT;

    float *bufA, *bufB, *inv_out, *inv_in, *s1, *zreg, *wt;
    cudaGetSymbolAddress((void**)&bufA,    g_bufA);
    cudaGetSymbolAddress((void**)&bufB,    g_bufB);
    cudaGetSymbolAddress((void**)&inv_out, g_inv_out);
    cudaGetSymbolAddress((void**)&inv_in,  g_inv_in);
    cudaGetSymbolAddress((void**)&s1,      g_s1);
    cudaGetSymbolAddress((void**)&zreg,    g_zregion);
    cudaGetSymbolAddress((void**)&wt,      g_Wt);

    cudaFuncSetAttribute(gemm0_kernel,
                         cudaFuncAttributeMaxDynamicSharedMemorySize, GSMEM);

    int nb = (n + 1023) / 1024;

    // 0. zero packed scratch + transpose W_ext -> g_Wt
    prep_kernel<<<148, 256>>>(W_ext, RAW);
    // 1. degree histograms
    degree_kernel<<<(E + 255) / 256, 256>>>(src, dst, E);
    // 2. per-chunk reduce + rsqrt factors + graph counts
    scanA_kernel<<<nb, 1024>>>(gid, n);
    // 3. GEMM0 (profiled slot): bufA = (fsnet @ W_ext + b_ext) * inv_out
    gemm0_kernel<<<(n + TM - 1) / TM, 256, GSMEM>>>(fsnet, wt, b_ext, inv_out, bufA, n, RAW);
    // 4/5. finish CSR offsets
    scanB_kernel<<<1, 128>>>(nb, n);
    scanC_kernel<<<nb, 1024>>>(n);
    // 6. CSR scatter (by dst)
    scatter_kernel<<<(E + 255) / 256, 256>>>(src, dst, E);
    // 7-9. fold weights
    wprec1_kernel<<<(LAT * H2 + 255) / 256, 256>>>(W1, W2);
    wprec2_kernel<<<(LAT * NCLASS + 255) / 256, 256>>>(Wc);
    wprec3_kernel<<<1, 256>>>(b1, W2, b2, Wc, bc);
    // 10. prop1 (+ fused dtilde on lane 25): bufB = P(x0) * s1
    int pblocks = (n * 32 + 255) / 256;
    prop_csr_kernel<false><<<pblocks, 256>>>((const float4*)bufA, (float4*)bufB, s1, gid, n);
    // 11. prop2 fused with graph pooling
    prop_csr_kernel<true><<<pblocks, 256>>>((const float4*)bufB, nullptr, inv_in, gid, n);
    // 12. out = (poolX/cnt) @ Wfin + (poolD/cnt) * v1 + c0
    final_kernel<<<NGRAPH, 128>>>(out);
}

// round 10
// speedup vs baseline: 1.3245x; 1.3245x over previous
#include <cuda_runtime.h>
#include <cstdint>

#define MAX_NODES 50000
#define LAT       100
#define NGRAPH    256
#define H2        200
#define NCLASS    55
#define D         56          // padded class dim (14 float4)
#define MAX_EDGES 800000
#define KMAX      512

typedef unsigned long long u64;

// ---------------- scratch (device globals) ---------------------------------
__device__ __align__(16) float g_bufA[MAX_NODES * D];     // z0 * inv_out
__device__ __align__(16) float g_bufB[MAX_NODES * D];     // P(z0) * s1
__device__ __align__(16) float g_inv_out[MAX_NODES];
__device__ __align__(16) float g_inv_in[MAX_NODES];
__device__ __align__(16) float g_s1[MAX_NODES];
__device__ __align__(16) int   g_off[MAX_NODES + 16];
__device__ __align__(16) int   g_cur[MAX_NODES];
__device__ __align__(16) int   g_csr[MAX_EDGES];
__device__ __align__(16) int   g_bsum[80];
__device__ __align__(16) int   g_bpre[80];
__device__ __align__(16) float g_W12[LAT * H2];           // W1 @ W2
__device__ __align__(16) float g_Wfin[LAT * NCLASS];      // W1 @ W2 @ Wc
__device__ __align__(16) float g_Wall[KMAX * D];          // W_ext @ Wfin (padded)
__device__ __align__(16) float g_bfold[64];               // b_ext @ Wfin (padded)
__device__ __align__(16) float g_v1[64];                  // b1 @ W2 @ Wc
__device__ __align__(16) float g_c0[64];                  // b2 @ Wc + bc

// packed zero region: out_deg(f32) | deg_in(i32) | poolX[256*56] | poolD | cnt
#define ZR_OUTDEG 0
#define ZR_DEGIN  50000
#define ZR_POOLX  100000
#define ZR_POOLD  114336
#define ZR_CNT    114592
#define ZR_TOTAL  114848
__device__ __align__(16) float g_zregion[ZR_TOTAL];

// ---------------- f32x2 packed math helpers --------------------------------
__device__ __forceinline__ void ffma2(u64& d, u64 a, u64 b) {
    asm("fma.rn.f32x2 %0, %1, %2, %0;" : "+l"(d) : "l"(a), "l"(b));
}
__device__ __forceinline__ float2 unpack2(u64 v) {
    float2 f; asm("mov.b64 {%0, %1}, %2;" : "=f"(f.x), "=f"(f.y) : "l"(v)); return f;
}
__device__ __forceinline__ u64 swap2(u64 v) {
    float2 f = unpack2(v);
    u64 r; asm("mov.b64 %0, {%1, %2};" : "=l"(r) : "f"(f.y), "f"(f.x));
    return r;
}

// ---------------- cp.async helpers -----------------------------------------
__device__ __forceinline__ void cp_async16(uint32_t saddr, const void* gptr) {
    asm volatile("cp.async.ca.shared.global [%0], [%1], 16;"
                 :: "r"(saddr), "l"(gptr));
}
__device__ __forceinline__ void cp_commit() {
    asm volatile("cp.async.commit_group;");
}
__device__ __forceinline__ void cp_wait_all() {
    asm volatile("cp.async.wait_group 0;");
}

// ---------------- prep: zero packed scratch ---------------------------------
__global__ void prep_kernel() {
    int i = blockIdx.x * blockDim.x + threadIdx.x;
    int stride = gridDim.x * blockDim.x;
    float4* z = (float4*)g_zregion;
    float4 zv = make_float4(0.f, 0.f, 0.f, 0.f);
    for (int t = i; t < ZR_TOTAL / 4; t += stride) z[t] = zv;
}

__global__ void degree_kernel(const int* __restrict__ src, const int* __restrict__ dst, int E) {
    float* out_deg = g_zregion + ZR_OUTDEG;
    int*   deg_in  = (int*)(g_zregion + ZR_DEGIN);
    int i = blockIdx.x * blockDim.x + threadIdx.x;
    if (i < E) {
        atomicAdd(&out_deg[src[i]], 1.0f);
        atomicAdd(&deg_in[dst[i]], 1);
    }
}

// scanA: per-chunk reduce of deg_in; also rsqrt factors + per-graph counts
__global__ void scanA_kernel(const int* __restrict__ gid, int n) {
    __shared__ int wsum[32];
    const float* out_deg = g_zregion + ZR_OUTDEG;
    const int*   deg_in  = (const int*)(g_zregion + ZR_DEGIN);
    float* cnt = g_zregion + ZR_CNT;
    int tid = threadIdx.x, lane = tid & 31, warp = tid >> 5;
    int i = blockIdx.x * 1024 + tid;
    int v = 0;
    if (i < n) {
        v = deg_in[i];
        float ii = rsqrtf(fmaxf((float)v, 1.0f));
        float io = rsqrtf(fmaxf(out_deg[i], 1.0f));
        g_inv_in[i]  = ii;
        g_inv_out[i] = io;
        g_s1[i]      = ii * io;
        atomicAdd(&cnt[gid[i]], 1.0f);
    }
    int s = v;
#pragma unroll
    for (int d = 16; d > 0; d >>= 1) s += __shfl_down_sync(0xffffffffu, s, d);
    if (lane == 0) wsum[warp] = s;
    __syncthreads();
    if (warp == 0) {
        int t = (lane < 32) ? wsum[lane] : 0;
#pragma unroll
        for (int d = 16; d > 0; d >>= 1) t += __shfl_down_sync(0xffffffffu, t, d);
        if (lane == 0) g_bsum[blockIdx.x] = t;
    }
}

__global__ void scanB_kernel(int nb, int n) {
    __shared__ int s[80];
    int tid = threadIdx.x;
    if (tid < nb) s[tid] = g_bsum[tid];
    __syncthreads();
    if (tid == 0) {
        int run = 0;
        for (int b = 0; b < nb; b++) { int t = s[b]; s[b] = run; run += t; }
        g_off[n] = run;
    }
    __syncthreads();
    if (tid < nb) g_bpre[tid] = s[tid];
}

__global__ void scanC_kernel(int n) {
    __shared__ int wsum[32];
    const int* deg_in = (const int*)(g_zregion + ZR_DEGIN);
    int tid = threadIdx.x, lane = tid & 31, warp = tid >> 5;
    int i = blockIdx.x * 1024 + tid;
    int v = (i < n) ? deg_in[i] : 0;
    int s = v;
#pragma unroll
    for (int d = 1; d < 32; d <<= 1) {
        int t = __shfl_up_sync(0xffffffffu, s, d);
        if (lane >= d) s += t;
    }
    if (lane == 31) wsum[warp] = s;
    __syncthreads();
    if (warp == 0) {
        int ws = wsum[lane];
#pragma unroll
        for (int d = 1; d < 32; d <<= 1) {
            int t = __shfl_up_sync(0xffffffffu, ws, d);
            if (lane >= d) ws += t;
        }
        wsum[lane] = ws;
    }
    __syncthreads();
    int wpre = (warp > 0) ? wsum[warp - 1] : 0;
    int excl = s - v + wpre + g_bpre[blockIdx.x];
    if (i < n) { g_off[i] = excl; g_cur[i] = excl; }
}

__global__ void scatter_kernel(const int* __restrict__ src, const int* __restrict__ dst, int E) {
    int i = blockIdx.x * blockDim.x + threadIdx.x;
    if (i < E) {
        int p = atomicAdd(&g_cur[dst[i]], 1);
        g_csr[p] = src[i];
    }
}

// ---------------- CSR propagation (56-dim rows, half-warp per node) --------
// lanes 0..13: gather 14 float4 chunks; lane 14 (prop1 only): dtilde.
template <bool POOL>
__global__ void prop_csr_kernel(const float4* __restrict__ xs,
                                float4* __restrict__ agg,
                                const float* __restrict__ scale,
                                const int* __restrict__ gid, int n) {
    int node = (blockIdx.x * blockDim.x + threadIdx.x) >> 4;
    int l = threadIdx.x & 15;
    if (node >= n) return;
    int b = g_off[node], e = g_off[node + 1];
    bool act = l < 14;
    bool dt  = (!POOL) && (l == 14);
    float4 a0 = make_float4(0.f, 0.f, 0.f, 0.f);
    float4 a1 = a0, a2 = a0, a3 = a0;
    float sd = 0.f;
    unsigned base = (unsigned)l;
    int k = b;
    for (; k + 4 <= e; k += 4) {
        int s0 = g_csr[k], s1 = g_csr[k + 1], s2 = g_csr[k + 2], s3 = g_csr[k + 3];
        if (act) {
            float4 v0 = xs[(unsigned)s0 * 14u + base];
            float4 v1 = xs[(unsigned)s1 * 14u + base];
            float4 v2 = xs[(unsigned)s2 * 14u + base];
            float4 v3 = xs[(unsigned)s3 * 14u + base];
            a0.x += v0.x; a0.y += v0.y; a0.z += v0.z; a0.w += v0.w;
            a1.x += v1.x; a1.y += v1.y; a1.z += v1.z; a1.w += v1.w;
            a2.x += v2.x; a2.y += v2.y; a2.z += v2.z; a2.w += v2.w;
            a3.x += v3.x; a3.y += v3.y; a3.z += v3.z; a3.w += v3.w;
        } else if (dt) {
            sd += g_inv_out[s0] + g_inv_out[s1] + g_inv_out[s2] + g_inv_out[s3];
        }
    }
    for (; k < e; k++) {
        int s0 = g_csr[k];
        if (act) {
            float4 v0 = xs[(unsigned)s0 * 14u + base];
            a0.x += v0.x; a0.y += v0.y; a0.z += v0.z; a0.w += v0.w;
        } else if (dt) {
            sd += g_inv_out[s0];
        }
    }
    if (act) {
        float sc = scale[node];
        float x = (a0.x + a1.x + a2.x + a3.x) * sc;
        float y = (a0.y + a1.y + a2.y + a3.y) * sc;
        float z = (a0.z + a1.z + a2.z + a3.z) * sc;
        float w = (a0.w + a1.w + a2.w + a3.w) * sc;
        if (!POOL) {
            agg[(unsigned)node * 14u + base] = make_float4(x, y, z, w);
        } else {
            float* poolX = g_zregion + ZR_POOLX;
            float* p = poolX + (unsigned)gid[node] * D + base * 4u;
            asm volatile("red.global.add.v4.f32 [%0], {%1,%2,%3,%4};"
                         :: "l"(p), "f"(x), "f"(y), "f"(z), "f"(w)
                         : "memory");
        }
    } else if (dt) {
        float* poolD = g_zregion + ZR_POOLD;
        atomicAdd(&poolD[gid[node]], sd * g_inv_in[node]);
    }
}

// ---------------- GEMM0: z0 = (fsnet @ Wall + bfold) .* inv_out -------------
// Round-8 structure, N=56: TM=128, KC=32, 3 blocks/SM. A staged via
// LDG->reg->transposed STS, W via cp.async natural. 224 workers,
// each 8 rows x 4 cols; per k: 3 LDS.128 + 2 swaps + 16 FFMA2.
#define TM 128
#define KC 32
#define SA 132
#define SW 60
#define ABUF (KC * SA)
#define WBUF (KC * SW)
#define GSMEM ((2 * ABUF + 2 * WBUF) * 4)
__global__ void __launch_bounds__(256, 3) gemm0_kernel(
        const float* __restrict__ A,
        const float* __restrict__ Wn,     // [K][D] folded weights
        const float* __restrict__ bias,   // bfold [D]
        const float* __restrict__ sout,
        float* __restrict__ C, int M, int K) {
    extern __shared__ float sm[];
    float* AsB = sm;                 // [2][KC][SA]
    float* WsB = sm + 2 * ABUF;      // [2][KC][SW]
    uint32_t wbase = (uint32_t)__cvta_generic_to_shared(WsB);

    int tid = threadIdx.x;
    int m0 = blockIdx.x * TM;
    bool worker = tid < 224;
    int ty = tid / 14;               // 0..15 for workers
    int tx = tid - ty * 14;          // 0..13
    int r0 = ty * 8;
    int c0 = tx * 4;

    u64 accd[4][2], accx[4][2];
#pragma unroll
    for (int p = 0; p < 4; p++) {
        accd[p][0] = accd[p][1] = 0ull;
        accx[p][0] = accx[p][1] = 0ull;
    }

    float4 aQ[4];
    int nk = (K + KC - 1) / KC;

    auto loadW = [&](int k0, int buf) {
#pragma unroll
        for (int s = 0; s < 2; s++) {
            int idx = tid + s * 256;
            if (idx < KC * 14) {
                int kk = idx / 14, c4 = idx - kk * 14;
                int gk = k0 + kk;
                uint32_t dst = wbase + (buf * WBUF + kk * SW + c4 * 4) * 4;
                if (gk < K) {
                    cp_async16(dst, &Wn[(size_t)gk * D + c4 * 4]);
                } else {
                    float* d = WsB + buf * WBUF + kk * SW + c4 * 4;
                    d[0] = d[1] = d[2] = d[3] = 0.f;
                }
            }
        }
    };
    auto loadA = [&](int k0) {
#pragma unroll
        for (int s = 0; s < 4; s++) {
            int idx = tid + s * 256;            // < 1024 = TM*KC/4
            int row = idx >> 3, q = idx & 7;
            int gr = m0 + row; if (gr >= M) gr = M - 1;
            int gk = k0 + q * 4;
            if (gk + 3 < K) {
                aQ[s] = *(const float4*)&A[(size_t)gr * K + gk];
            } else {
                aQ[s].x = (gk     < K) ? A[(size_t)gr * K + gk]     : 0.f;
                aQ[s].y = (gk + 1 < K) ? A[(size_t)gr * K + gk + 1] : 0.f;
                aQ[s].z = (gk + 2 < K) ? A[(size_t)gr * K + gk + 2] : 0.f;
                aQ[s].w = (gk + 3 < K) ? A[(size_t)gr * K + gk + 3] : 0.f;
            }
        }
    };
    auto storeA = [&](int buf) {
        float* Ab = AsB + buf * ABUF;
#pragma unroll
        for (int s = 0; s < 4; s++) {
            int idx = tid + s * 256;
            int row = idx >> 3, q = idx & 7;
            float* dst = Ab + (q * 4) * SA + row;
            dst[0] = aQ[s].x; dst[SA] = aQ[s].y; dst[2 * SA] = aQ[s].z; dst[3 * SA] = aQ[s].w;
        }
    };

    // prologue: chunk 0
    loadW(0, 0);
    cp_commit();
    loadA(0);
    storeA(0);
    cp_wait_all();
    __syncthreads();

    for (int ch = 0; ch < nk; ch++) {
        int buf = ch & 1;
        if (ch + 1 < nk) {
            loadA((ch + 1) * KC);
            loadW((ch + 1) * KC, buf ^ 1);
            cp_commit();
        }
        if (worker) {
            const float* Ab = AsB + buf * ABUF;
            const float* Wb = WsB + buf * WBUF;
#pragma unroll 4
            for (int k = 0; k < KC; k++) {
                ulonglong2 a01 = *(const ulonglong2*)(Ab + k * SA + r0);
                ulonglong2 a23 = *(const ulonglong2*)(Ab + k * SA + r0 + 4);
                ulonglong2 w   = *(const ulonglong2*)(Wb + k * SW + c0);
                u64 wxs = swap2(w.x);
                u64 wys = swap2(w.y);
                ffma2(accd[0][0], a01.x, w.x);  ffma2(accx[0][0], a01.x, wxs);
                ffma2(accd[0][1], a01.x, w.y);  ffma2(accx[0][1], a01.x, wys);
                ffma2(accd[1][0], a01.y, w.x);  ffma2(accx[1][0], a01.y, wxs);
                ffma2(accd[1][1], a01.y, w.y);  ffma2(accx[1][1], a01.y, wys);
                ffma2(accd[2][0], a23.x, w.x);  ffma2(accx[2][0], a23.x, wxs);
                ffma2(accd[2][1], a23.x, w.y);  ffma2(accx[2][1], a23.x, wys);
                ffma2(accd[3][0], a23.y, w.x);  ffma2(accx[3][0], a23.y, wxs);
                ffma2(accd[3][1], a23.y, w.y);  ffma2(accx[3][1], a23.y, wys);
            }
        }
        if (ch + 1 < nk) {
            storeA(buf ^ 1);
            cp_wait_all();
            __syncthreads();
        }
    }

    if (worker) {
        float4 bv = *(const float4*)&bias[c0];
#pragma unroll
        for (int p = 0; p < 4; p++) {
            float2 d0 = unpack2(accd[p][0]);
            float2 x0 = unpack2(accx[p][0]);
            float2 d1 = unpack2(accd[p][1]);
            float2 x1 = unpack2(accx[p][1]);
            int row = m0 + r0 + 2 * p;
            if (row < M) {
                float so = sout[row];
                float4 v = make_float4((d0.x + bv.x) * so, (x0.x + bv.y) * so,
                                       (d1.x + bv.z) * so, (x1.x + bv.w) * so);
                *(float4*)&C[(size_t)row * D + c0] = v;
            }
            if (row + 1 < M) {
                float so = sout[row + 1];
                float4 v = make_float4((x0.y + bv.x) * so, (d0.y + bv.y) * so,
                                       (x1.y + bv.z) * so, (d1.y + bv.w) * so);
                *(float4*)&C[(size_t)(row + 1) * D + c0] = v;
            }
        }
    }
}

// ---------------- weight folding (all tiny) --------------------------------
__global__ void wprec1_kernel(const float* __restrict__ W1, const float* __restrict__ W2) {
    int idx = blockIdx.x * blockDim.x + threadIdx.x;
    if (idx >= LAT * H2) return;
    int i = idx / H2, j = idx % H2;
    float acc = 0.f;
    for (int k = 0; k < LAT; k++) acc += W1[i * LAT + k] * W2[k * H2 + j];
    g_W12[idx] = acc;
}
__global__ void wprec2_kernel(const float* __restrict__ Wc) {
    int idx = blockIdx.x * blockDim.x + threadIdx.x;
    if (idx >= LAT * NCLASS) return;
    int i = idx / NCLASS, j = idx % NCLASS;
    float acc = 0.f;
    for (int k = 0; k < H2; k++) acc += g_W12[i * H2 + k] * Wc[k * NCLASS + j];
    g_Wfin[idx] = acc;
}
// Wall[K][D] = W_ext[K][100] @ Wfin[100][55]  (col 55 zero-padded)
__global__ void wprecA_kernel(const float* __restrict__ W_ext, int K) {
    int idx = blockIdx.x * blockDim.x + threadIdx.x;
    if (idx >= K * D) return;
    int i = idx / D, c = idx - i * D;
    float acc = 0.f;
    if (c < NCLASS)
        for (int k = 0; k < LAT; k++) acc += W_ext[i * LAT + k] * g_Wfin[k * NCLASS + c];
    g_Wall[idx] = acc;
}
// v1 = b1@W2@Wc ; c0 = b2@Wc + bc ; bfold = b_ext@Wfin (padded)
__global__ void wprec3_kernel(const float* __restrict__ b1, const float* __restrict__ W2,
                              const float* __restrict__ b2, const float* __restrict__ Wc,
                              const float* __restrict__ bc, const float* __restrict__ b_ext) {
    __shared__ float bw2[H2];
    int tid = threadIdx.x;
    for (int k = tid; k < H2; k += blockDim.x) {
        float acc = 0.f;
        for (int j = 0; j < LAT; j++) acc += b1[j] * W2[j * H2 + k];
        bw2[k] = acc;
    }
    __syncthreads();
    if (tid < D) {
        float bf = 0.f;
        if (tid < NCLASS)
            for (int k = 0; k < LAT; k++) bf += b_ext[k] * g_Wfin[k * NCLASS + tid];
        g_bfold[tid] = bf;
    }
    if (tid < NCLASS) {
        float v = 0.f, c = 0.f;
        for (int k = 0; k < H2; k++) {
            v += bw2[k] * Wc[k * NCLASS + tid];
            c += b2[k] * Wc[k * NCLASS + tid];
        }
        g_v1[tid] = v;
        g_c0[tid] = c + bc[tid];
    }
}

// ---------------- final: out[g,c] = poolX/cnt + (poolD/cnt)*v1 + c0 --------
__global__ void final_kernel(float* __restrict__ out) {
    const float* poolX = g_zregion + ZR_POOLX;
    const float* poolD = g_zregion + ZR_POOLD;
    const float* cnt   = g_zregion + ZR_CNT;
    int g = blockIdx.x, tid = threadIdx.x;
    if (tid < NCLASS) {
        float invc = 1.0f / fmaxf(cnt[g], 1.0f);
        out[g * NCLASS + tid] = poolX[g * D + tid] * invc
                              + poolD[g] * invc * g_v1[tid]
                              + g_c0[tid];
    }
}

// ---------------- launch ---------------------------------------------------
extern "C" void kernel_launch(void* const* d_in, const int* in_sizes, int n_in,
                              void* d_out, int out_size) {
    const float* fsnet = (const float*)d_in[0];
    const int*   src   = (const int*)d_in[1];
    const int*   dst   = (const int*)d_in[2];
    const int*   gid   = (const int*)d_in[3];
    const float* W_ext = (const float*)d_in[4];
    const float* b_ext = (const float*)d_in[5];
    const float* W1    = (const float*)d_in[6];
    const float* b1    = (const float*)d_in[7];
    const float* W2    = (const float*)d_in[8];
    const float* b2    = (const float*)d_in[9];
    const float* Wc    = (const float*)d_in[10];
    const float* bc    = (const float*)d_in[11];
    float* out = (float*)d_out;

    int n   = in_sizes[3];
    int E   = in_sizes[1];
    int RAW = in_sizes[4] / LAT;

    float *bufA, *bufB, *inv_out, *inv_in, *s1, *wall, *bfold;
    cudaGetSymbolAddress((void**)&bufA,    g_bufA);
    cudaGetSymbolAddress((void**)&bufB,    g_bufB);
    cudaGetSymbolAddress((void**)&inv_out, g_inv_out);
    cudaGetSymbolAddress((void**)&inv_in,  g_inv_in);
    cudaGetSymbolAddress((void**)&s1,      g_s1);
    cudaGetSymbolAddress((void**)&wall,    g_Wall);
    cudaGetSymbolAddress((void**)&bfold,   g_bfold);

    cudaFuncSetAttribute(gemm0_kernel,
                         cudaFuncAttributeMaxDynamicSharedMemorySize, GSMEM);

    int nb = (n + 1023) / 1024;

    // 0. zero packed scratch
    prep_kernel<<<148, 256>>>();
    // 1. degree histograms
    degree_kernel<<<(E + 255) / 256, 256>>>(src, dst, E);
    // 2. per-chunk reduce + rsqrt factors + graph counts
    scanA_kernel<<<nb, 1024>>>(gid, n);
    // 3-6. fold ALL weights into class space (before gemm0)
    wprec1_kernel<<<(LAT * H2 + 255) / 256, 256>>>(W1, W2);
    wprec2_kernel<<<(LAT * NCLASS + 255) / 256, 256>>>(Wc);
    wprecA_kernel<<<(RAW * D + 255) / 256, 256>>>(W_ext, RAW);
    wprec3_kernel<<<1, 256>>>(b1, W2, b2, Wc, bc, b_ext);
    // 7. GEMM0: bufA = (fsnet @ Wall + bfold) * inv_out   [50000 x 56]
    gemm0_kernel<<<(n + TM - 1) / TM, 256, GSMEM>>>(fsnet, wall, bfold, inv_out, bufA, n, RAW);
    // 8/9. finish CSR offsets
    scanB_kernel<<<1, 128>>>(nb, n);
    scanC_kernel<<<nb, 1024>>>(n);
    // 10. CSR scatter (by dst)
    scatter_kernel<<<(E + 255) / 256, 256>>>(src, dst, E);
    // 11. prop1 (+ fused dtilde on lane 14): bufB = P(z0) * s1
    int pblocks = (n * 16 + 255) / 256;
    prop_csr_kernel<false><<<pblocks, 256>>>((const float4*)bufA, (float4*)bufB, s1, gid, n);
    // 12. prop2 fused with graph pooling
    prop_csr_kernel<true><<<pblocks, 256>>>((const float4*)bufB, nullptr, inv_in, gid, n);
    // 13. out = poolX/cnt + (poolD/cnt)*v1 + c0
    final_kernel<<<NGRAPH, 64>>>(out);
}

// round 11
// speedup vs baseline: 1.6309x; 1.2314x over previous
#include <cuda_runtime.h>
#include <cstdint>

#define MAX_NODES 50000
#define LAT       100
#define NGRAPH    256
#define H2        200
#define NCLASS    55
#define D         56          // padded class dim (14 float4)
#define MAX_EDGES 800000
#define KMAX      512

typedef unsigned long long u64;

// ---------------- scratch (device globals) ---------------------------------
__device__ __align__(16) float g_bufA[MAX_NODES * D];
__device__ __align__(16) float g_bufB[MAX_NODES * D];
__device__ __align__(16) float g_inv_out[MAX_NODES];
__device__ __align__(16) float g_inv_in[MAX_NODES];
__device__ __align__(16) float g_s1[MAX_NODES];
__device__ __align__(16) int   g_off[MAX_NODES + 16];
__device__ __align__(16) int   g_cur[MAX_NODES];
__device__ __align__(16) int   g_csr[MAX_EDGES];
__device__ __align__(16) int   g_bsum[80];
__device__ __align__(16) int   g_bpre[80];
__device__ __align__(16) float g_T1[LAT * D];             // W2 @ Wc (padded)
__device__ __align__(16) float g_Wfin[LAT * D];           // W1 @ T1 (padded)
__device__ __align__(16) float g_Wall[KMAX * D];          // W_ext @ Wfin
__device__ __align__(16) float g_bfold[64];               // b_ext @ Wfin
__device__ __align__(16) float g_v1[64];                  // b1 @ T1
__device__ __align__(16) float g_c0[64];                  // b2 @ Wc + bc

// packed zero region: out_deg(f32) | deg_in(i32) | poolX[256*56] | poolD | cnt
#define ZR_OUTDEG 0
#define ZR_DEGIN  50000
#define ZR_POOLX  100000
#define ZR_POOLD  114336
#define ZR_CNT    114592
#define ZR_TOTAL  114848
__device__ __align__(16) float g_zregion[ZR_TOTAL];

// ---------------- f32x2 packed math helpers --------------------------------
__device__ __forceinline__ void ffma2(u64& d, u64 a, u64 b) {
    asm("fma.rn.f32x2 %0, %1, %2, %0;" : "+l"(d) : "l"(a), "l"(b));
}
__device__ __forceinline__ float2 unpack2(u64 v) {
    float2 f; asm("mov.b64 {%0, %1}, %2;" : "=f"(f.x), "=f"(f.y) : "l"(v)); return f;
}
__device__ __forceinline__ u64 swap2(u64 v) {
    float2 f = unpack2(v);
    u64 r; asm("mov.b64 %0, {%1, %2};" : "=l"(r) : "f"(f.y), "f"(f.x));
    return r;
}

// ---------------- cp.async helpers -----------------------------------------
__device__ __forceinline__ void cp_async16(uint32_t saddr, const void* gptr) {
    asm volatile("cp.async.ca.shared.global [%0], [%1], 16;"
                 :: "r"(saddr), "l"(gptr));
}
__device__ __forceinline__ void cp_commit() {
    asm volatile("cp.async.commit_group;");
}
__device__ __forceinline__ void cp_wait_all() {
    asm volatile("cp.async.wait_group 0;");
}

// ---------------- L1: prep (zero packed scratch) ----------------------------
__global__ void prep_kernel() {
    int i = blockIdx.x * blockDim.x + threadIdx.x;
    int stride = gridDim.x * blockDim.x;
    float4* z = (float4*)g_zregion;
    float4 zv = make_float4(0.f, 0.f, 0.f, 0.f);
    for (int t = i; t < ZR_TOTAL / 4; t += stride) z[t] = zv;
}

// ---------------- L2: degree histograms || T1 = W2 @ Wc ---------------------
#define WT_BLK 22   // ceil(100*56/256)
__global__ void fuse_deg_wT_kernel(const int* __restrict__ src,
                                   const int* __restrict__ dst, int E,
                                   const float* __restrict__ W2,
                                   const float* __restrict__ Wc) {
    if (blockIdx.x < WT_BLK) {
        int idx = blockIdx.x * 256 + threadIdx.x;
        if (idx < LAT * D) {
            int i = idx / D, j = idx - i * D;
            float a0 = 0.f, a1 = 0.f;
            if (j < NCLASS) {
                const float* w2r = W2 + i * H2;
#pragma unroll 4
                for (int k = 0; k < H2; k += 2) {
                    a0 += w2r[k]     * Wc[k * NCLASS + j];
                    a1 += w2r[k + 1] * Wc[(k + 1) * NCLASS + j];
                }
            }
            g_T1[idx] = a0 + a1;
        }
    } else {
        int i = (blockIdx.x - WT_BLK) * 256 + threadIdx.x;
        if (i < E) {
            float* out_deg = g_zregion + ZR_OUTDEG;
            int*   deg_in  = (int*)(g_zregion + ZR_DEGIN);
            atomicAdd(&out_deg[src[i]], 1.0f);
            atomicAdd(&deg_in[dst[i]], 1);
        }
    }
}

// ---------------- L3: scanA || Wfin = W1 @ T1 --------------------------------
#define WF_BLK 6    // ceil(100*56/1024)
__global__ void fuse_scanA_wF_kernel(const int* __restrict__ gid, int n,
                                     const float* __restrict__ W1) {
    if (blockIdx.x < WF_BLK) {
        int idx = blockIdx.x * 1024 + threadIdx.x;
        if (idx < LAT * D) {
            int i = idx / D, j = idx - i * D;
            const float* w1r = W1 + i * LAT;
            float a0 = 0.f, a1 = 0.f;
#pragma unroll 4
            for (int k = 0; k < LAT; k += 2) {
                a0 += w1r[k]     * g_T1[k * D + j];
                a1 += w1r[k + 1] * g_T1[(k + 1) * D + j];
            }
            g_Wfin[idx] = a0 + a1;
        }
        return;
    }
    __shared__ int wsum[32];
    const float* out_deg = g_zregion + ZR_OUTDEG;
    const int*   deg_in  = (const int*)(g_zregion + ZR_DEGIN);
    float* cnt = g_zregion + ZR_CNT;
    int bb = blockIdx.x - WF_BLK;
    int tid = threadIdx.x, lane = tid & 31, warp = tid >> 5;
    int i = bb * 1024 + tid;
    int v = 0;
    if (i < n) {
        v = deg_in[i];
        float ii = rsqrtf(fmaxf((float)v, 1.0f));
        float io = rsqrtf(fmaxf(out_deg[i], 1.0f));
        g_inv_in[i]  = ii;
        g_inv_out[i] = io;
        g_s1[i]      = ii * io;
        atomicAdd(&cnt[gid[i]], 1.0f);
    }
    int s = v;
#pragma unroll
    for (int d = 16; d > 0; d >>= 1) s += __shfl_down_sync(0xffffffffu, s, d);
    if (lane == 0) wsum[warp] = s;
    __syncthreads();
    if (warp == 0) {
        int t = (lane < 32) ? wsum[lane] : 0;
#pragma unroll
        for (int d = 16; d > 0; d >>= 1) t += __shfl_down_sync(0xffffffffu, t, d);
        if (lane == 0) g_bsum[bb] = t;
    }
}

// ---------------- L4: scanB || Wall = W_ext @ Wfin || biases -----------------
__global__ void fuse_misc_kernel(int nb, int n,
                                 const float* __restrict__ W_ext, int RAW,
                                 const float* __restrict__ b1,
                                 const float* __restrict__ b2,
                                 const float* __restrict__ Wc,
                                 const float* __restrict__ bc,
                                 const float* __restrict__ b_ext,
                                 int nA) {
    int tid = threadIdx.x;
    if (blockIdx.x == 0) {
        // scanB: exclusive scan of block sums
        __shared__ int s[80];
        if (tid < nb) s[tid] = g_bsum[tid];
        __syncthreads();
        if (tid == 0) {
            int run = 0;
            for (int b = 0; b < nb; b++) { int t = s[b]; s[b] = run; run += t; }
            g_off[n] = run;
        }
        __syncthreads();
        if (tid < nb) g_bpre[tid] = s[tid];
    } else if (blockIdx.x <= nA) {
        // Wall
        int idx = (blockIdx.x - 1) * 256 + tid;
        if (idx < RAW * D) {
            int i = idx / D, c = idx - i * D;
            const float* wer = W_ext + i * LAT;
            float a0 = 0.f, a1 = 0.f;
#pragma unroll 4
            for (int k = 0; k < LAT; k += 2) {
                a0 += wer[k]     * g_Wfin[k * D + c];
                a1 += wer[k + 1] * g_Wfin[(k + 1) * D + c];
            }
            g_Wall[idx] = a0 + a1;
        }
    } else {
        // biases: v1 = b1@T1 ; bfold = b_ext@Wfin ; c0 = b2@Wc + bc
        int j = tid;
        if (j < D) {
            float v = 0.f, bf = 0.f;
            for (int k = 0; k < LAT; k++) {
                v  += b1[k]    * g_T1[k * D + j];
                bf += b_ext[k] * g_Wfin[k * D + j];
            }
            g_v1[j] = v;
            g_bfold[j] = bf;
            if (j < NCLASS) {
                float c = 0.f;
                for (int k = 0; k < H2; k++) c += b2[k] * Wc[k * NCLASS + j];
                g_c0[j] = c + bc[j];
            }
        }
    }
}

// ---------------- L5: scanC --------------------------------------------------
__global__ void scanC_kernel(int n) {
    __shared__ int wsum[32];
    const int* deg_in = (const int*)(g_zregion + ZR_DEGIN);
    int tid = threadIdx.x, lane = tid & 31, warp = tid >> 5;
    int i = blockIdx.x * 1024 + tid;
    int v = (i < n) ? deg_in[i] : 0;
    int s = v;
#pragma unroll
    for (int d = 1; d < 32; d <<= 1) {
        int t = __shfl_up_sync(0xffffffffu, s, d);
        if (lane >= d) s += t;
    }
    if (lane == 31) wsum[warp] = s;
    __syncthreads();
    if (warp == 0) {
        int ws = wsum[lane];
#pragma unroll
        for (int d = 1; d < 32; d <<= 1) {
            int t = __shfl_up_sync(0xffffffffu, ws, d);
            if (lane >= d) ws += t;
        }
        wsum[lane] = ws;
    }
    __syncthreads();
    int wpre = (warp > 0) ? wsum[warp - 1] : 0;
    int excl = s - v + wpre + g_bpre[blockIdx.x];
    if (i < n) { g_off[i] = excl; g_cur[i] = excl; }
}

// ---------------- L6: GEMM0 || CSR scatter -----------------------------------
// gemm blocks [0, gb): z0 = (fsnet @ Wall + bfold) * inv_out  (round-8 core)
// scatter blocks [gb, gb+eb): CSR build
#define TM 128
#define KC 32
#define SA 132
#define SW 60
#define ABUF (KC * SA)
#define WBUF (KC * SW)
#define GSMEM ((2 * ABUF + 2 * WBUF) * 4)
__global__ void __launch_bounds__(256, 3) fuse_gemm_scatter_kernel(
        const float* __restrict__ A,
        const float* __restrict__ Wn,
        const float* __restrict__ bias,
        const float* __restrict__ sout,
        float* __restrict__ C, int M, int K, int gb,
        const int* __restrict__ src, const int* __restrict__ dst, int E) {
    if (blockIdx.x >= gb) {
        int i = (blockIdx.x - gb) * 256 + threadIdx.x;
        if (i < E) {
            int p = atomicAdd(&g_cur[dst[i]], 1);
            g_csr[p] = src[i];
        }
        return;
    }
    extern __shared__ float sm[];
    float* AsB = sm;
    float* WsB = sm + 2 * ABUF;
    uint32_t wbase = (uint32_t)__cvta_generic_to_shared(WsB);

    int tid = threadIdx.x;
    int m0 = blockIdx.x * TM;
    bool worker = tid < 224;
    int ty = tid / 14;
    int tx = tid - ty * 14;
    int r0 = ty * 8;
    int c0 = tx * 4;

    u64 accd[4][2], accx[4][2];
#pragma unroll
    for (int p = 0; p < 4; p++) {
        accd[p][0] = accd[p][1] = 0ull;
        accx[p][0] = accx[p][1] = 0ull;
    }

    float4 aQ[4];
    int nk = (K + KC - 1) / KC;

    auto loadW = [&](int k0, int buf) {
#pragma unroll
        for (int s = 0; s < 2; s++) {
            int idx = tid + s * 256;
            if (idx < KC * 14) {
                int kk = idx / 14, c4 = idx - kk * 14;
                int gk = k0 + kk;
                uint32_t dstp = wbase + (buf * WBUF + kk * SW + c4 * 4) * 4;
                if (gk < K) {
                    cp_async16(dstp, &Wn[(size_t)gk * D + c4 * 4]);
                } else {
                    float* d = WsB + buf * WBUF + kk * SW + c4 * 4;
                    d[0] = d[1] = d[2] = d[3] = 0.f;
                }
            }
        }
    };
    auto loadA = [&](int k0) {
#pragma unroll
        for (int s = 0; s < 4; s++) {
            int idx = tid + s * 256;
            int row = idx >> 3, q = idx & 7;
            int gr = m0 + row; if (gr >= M) gr = M - 1;
            int gk = k0 + q * 4;
            if (gk + 3 < K) {
                aQ[s] = *(const float4*)&A[(size_t)gr * K + gk];
            } else {
                aQ[s].x = (gk     < K) ? A[(size_t)gr * K + gk]     : 0.f;
                aQ[s].y = (gk + 1 < K) ? A[(size_t)gr * K + gk + 1] : 0.f;
                aQ[s].z = (gk + 2 < K) ? A[(size_t)gr * K + gk + 2] : 0.f;
                aQ[s].w = (gk + 3 < K) ? A[(size_t)gr * K + gk + 3] : 0.f;
            }
        }
    };
    auto storeA = [&](int buf) {
        float* Ab = AsB + buf * ABUF;
#pragma unroll
        for (int s = 0; s < 4; s++) {
            int idx = tid + s * 256;
            int row = idx >> 3, q = idx & 7;
            float* dstp = Ab + (q * 4) * SA + row;
            dstp[0] = aQ[s].x; dstp[SA] = aQ[s].y; dstp[2 * SA] = aQ[s].z; dstp[3 * SA] = aQ[s].w;
        }
    };

    loadW(0, 0);
    cp_commit();
    loadA(0);
    storeA(0);
    cp_wait_all();
    __syncthreads();

    for (int ch = 0; ch < nk; ch++) {
        int buf = ch & 1;
        if (ch + 1 < nk) {
            loadA((ch + 1) * KC);
            loadW((ch + 1) * KC, buf ^ 1);
            cp_commit();
        }
        if (worker) {
            const float* Ab = AsB + buf * ABUF;
            const float* Wb = WsB + buf * WBUF;
#pragma unroll 4
            for (int k = 0; k < KC; k++) {
                ulonglong2 a01 = *(const ulonglong2*)(Ab + k * SA + r0);
                ulonglong2 a23 = *(const ulonglong2*)(Ab + k * SA + r0 + 4);
                ulonglong2 w   = *(const ulonglong2*)(Wb + k * SW + c0);
                u64 wxs = swap2(w.x);
                u64 wys = swap2(w.y);
                ffma2(accd[0][0], a01.x, w.x);  ffma2(accx[0][0], a01.x, wxs);
                ffma2(accd[0][1], a01.x, w.y);  ffma2(accx[0][1], a01.x, wys);
                ffma2(accd[1][0], a01.y, w.x);  ffma2(accx[1][0], a01.y, wxs);
                ffma2(accd[1][1], a01.y, w.y);  ffma2(accx[1][1], a01.y, wys);
                ffma2(accd[2][0], a23.x, w.x);  ffma2(accx[2][0], a23.x, wxs);
                ffma2(accd[2][1], a23.x, w.y);  ffma2(accx[2][1], a23.x, wys);
                ffma2(accd[3][0], a23.y, w.x);  ffma2(accx[3][0], a23.y, wxs);
                ffma2(accd[3][1], a23.y, w.y);  ffma2(accx[3][1], a23.y, wys);
            }
        }
        if (ch + 1 < nk) {
            storeA(buf ^ 1);
            cp_wait_all();
            __syncthreads();
        }
    }

    if (worker) {
        float4 bv = *(const float4*)&bias[c0];
#pragma unroll
        for (int p = 0; p < 4; p++) {
            float2 d0 = unpack2(accd[p][0]);
            float2 x0 = unpack2(accx[p][0]);
            float2 d1 = unpack2(accd[p][1]);
            float2 x1 = unpack2(accx[p][1]);
            int row = m0 + r0 + 2 * p;
            if (row < M) {
                float so = sout[row];
                float4 v = make_float4((d0.x + bv.x) * so, (x0.x + bv.y) * so,
                                       (d1.x + bv.z) * so, (x1.x + bv.w) * so);
                *(float4*)&C[(size_t)row * D + c0] = v;
            }
            if (row + 1 < M) {
                float so = sout[row + 1];
                float4 v = make_float4((x0.y + bv.x) * so, (d0.y + bv.y) * so,
                                       (x1.y + bv.z) * so, (d1.y + bv.w) * so);
                *(float4*)&C[(size_t)(row + 1) * D + c0] = v;
            }
        }
    }
}

// ---------------- L7/L8: CSR propagation (56-dim, half-warp per node) -------
template <bool POOL>
__global__ void prop_csr_kernel(const float4* __restrict__ xs,
                                float4* __restrict__ agg,
                                const float* __restrict__ scale,
                                const int* __restrict__ gid, int n) {
    int node = (blockIdx.x * blockDim.x + threadIdx.x) >> 4;
    int l = threadIdx.x & 15;
    if (node >= n) return;
    int b = g_off[node], e = g_off[node + 1];
    bool act = l < 14;
    bool dt  = (!POOL) && (l == 14);
    float4 a0 = make_float4(0.f, 0.f, 0.f, 0.f);
    float4 a1 = a0, a2 = a0, a3 = a0;
    float sd = 0.f;
    unsigned base = (unsigned)l;
    int k = b;
    for (; k + 4 <= e; k += 4) {
        int s0 = g_csr[k], s1 = g_csr[k + 1], s2 = g_csr[k + 2], s3 = g_csr[k + 3];
        if (act) {
            float4 v0 = xs[(unsigned)s0 * 14u + base];
            float4 v1 = xs[(unsigned)s1 * 14u + base];
            float4 v2 = xs[(unsigned)s2 * 14u + base];
            float4 v3 = xs[(unsigned)s3 * 14u + base];
            a0.x += v0.x; a0.y += v0.y; a0.z += v0.z; a0.w += v0.w;
            a1.x += v1.x; a1.y += v1.y; a1.z += v1.z; a1.w += v1.w;
            a2.x += v2.x; a2.y += v2.y; a2.z += v2.z; a2.w += v2.w;
            a3.x += v3.x; a3.y += v3.y; a3.z += v3.z; a3.w += v3.w;
        } else if (dt) {
            sd += g_inv_out[s0] + g_inv_out[s1] + g_inv_out[s2] + g_inv_out[s3];
        }
    }
    for (; k < e; k++) {
        int s0 = g_csr[k];
        if (act) {
            float4 v0 = xs[(unsigned)s0 * 14u + base];
            a0.x += v0.x; a0.y += v0.y; a0.z += v0.z; a0.w += v0.w;
        } else if (dt) {
            sd += g_inv_out[s0];
        }
    }
    if (act) {
        float sc = scale[node];
        float x = (a0.x + a1.x + a2.x + a3.x) * sc;
        float y = (a0.y + a1.y + a2.y + a3.y) * sc;
        float z = (a0.z + a1.z + a2.z + a3.z) * sc;
        float w = (a0.w + a1.w + a2.w + a3.w) * sc;
        if (!POOL) {
            agg[(unsigned)node * 14u + base] = make_float4(x, y, z, w);
        } else {
            float* poolX = g_zregion + ZR_POOLX;
            float* p = poolX + (unsigned)gid[node] * D + base * 4u;
            asm volatile("red.global.add.v4.f32 [%0], {%1,%2,%3,%4};"
                         :: "l"(p), "f"(x), "f"(y), "f"(z), "f"(w)
                         : "memory");
        }
    } else if (dt) {
        float* poolD = g_zregion + ZR_POOLD;
        atomicAdd(&poolD[gid[node]], sd * g_inv_in[node]);
    }
}

// ---------------- L9: final --------------------------------------------------
__global__ void final_kernel(float* __restrict__ out) {
    const float* poolX = g_zregion + ZR_POOLX;
    const float* poolD = g_zregion + ZR_POOLD;
    const float* cnt   = g_zregion + ZR_CNT;
    int g = blockIdx.x, tid = threadIdx.x;
    if (tid < NCLASS) {
        float invc = 1.0f / fmaxf(cnt[g], 1.0f);
        out[g * NCLASS + tid] = poolX[g * D + tid] * invc
                              + poolD[g] * invc * g_v1[tid]
                              + g_c0[tid];
    }
}

// ---------------- launch ---------------------------------------------------
extern "C" void kernel_launch(void* const* d_in, const int* in_sizes, int n_in,
                              void* d_out, int out_size) {
    const float* fsnet = (const float*)d_in[0];
    const int*   src   = (const int*)d_in[1];
    const int*   dst   = (const int*)d_in[2];
    const int*   gid   = (const int*)d_in[3];
    const float* W_ext = (const float*)d_in[4];
    const float* b_ext = (const float*)d_in[5];
    const float* W1    = (const float*)d_in[6];
    const float* b1    = (const float*)d_in[7];
    const float* W2    = (const float*)d_in[8];
    const float* b2    = (const float*)d_in[9];
    const float* Wc    = (const float*)d_in[10];
    const float* bc    = (const float*)d_in[11];
    float* out = (float*)d_out;

    int n   = in_sizes[3];
    int E   = in_sizes[1];
    int RAW = in_sizes[4] / LAT;

    float *bufA, *bufB, *inv_out, *inv_in, *s1, *wall, *bfold;
    cudaGetSymbolAddress((void**)&bufA,    g_bufA);
    cudaGetSymbolAddress((void**)&bufB,    g_bufB);
    cudaGetSymbolAddress((void**)&inv_out, g_inv_out);
    cudaGetSymbolAddress((void**)&inv_in,  g_inv_in);
    cudaGetSymbolAddress((void**)&s1,      g_s1);
    cudaGetSymbolAddress((void**)&wall,    g_Wall);
    cudaGetSymbolAddress((void**)&bfold,   g_bfold);

    cudaFuncSetAttribute(fuse_gemm_scatter_kernel,
                         cudaFuncAttributeMaxDynamicSharedMemorySize, GSMEM);

    int nb = (n + 1023) / 1024;          // scanA/scanC blocks
    int eb = (E + 255) / 256;            // edge blocks
    int gb = (n + TM - 1) / TM;          // gemm blocks
    int nA = (RAW * D + 255) / 256;      // Wall blocks

    // L1: zero packed scratch
    prep_kernel<<<148, 256>>>();
    // L2: degree histograms || T1 = W2@Wc
    fuse_deg_wT_kernel<<<WT_BLK + eb, 256>>>(src, dst, E, W2, Wc);
    // L3: scanA (rsqrt + counts + block sums) || Wfin = W1@T1
    fuse_scanA_wF_kernel<<<WF_BLK + nb, 1024>>>(gid, n, W1);
    // L4: scanB || Wall = W_ext@Wfin || bias folds
    fuse_misc_kernel<<<1 + nA + 1, 256>>>(nb, n, W_ext, RAW, b1, b2, Wc, bc, b_ext, nA);
    // L5: scanC -> offsets
    scanC_kernel<<<nb, 1024>>>(n);
    // L6: GEMM0 || CSR scatter
    fuse_gemm_scatter_kernel<<<gb + eb, 256, GSMEM>>>(
        fsnet, wall, bfold, inv_out, bufA, n, RAW, gb, src, dst, E);
    // L7: prop1 (+ fused dtilde): bufB = P(z0) * s1
    int pblocks = (n * 16 + 255) / 256;
    prop_csr_kernel<false><<<pblocks, 256>>>((const float4*)bufA, (float4*)bufB, s1, gid, n);
    // L8: prop2 fused with graph pooling
    prop_csr_kernel<true><<<pblocks, 256>>>((const float4*)bufB, nullptr, inv_in, gid, n);
    // L9: out = poolX/cnt + (poolD/cnt)*v1 + c0
    final_kernel<<<NGRAPH, 64>>>(out);
}

// round 12
// speedup vs baseline: 1.6952x; 1.0394x over previous
#include <cuda_runtime.h>
#include <cstdint>

#define MAX_NODES 50000
#define LAT       100
#define NGRAPH    256
#define H2        200
#define NCLASS    55
#define D         56          // padded class dim (14 float4)
#define MAX_EDGES 800000
#define KMAX      512

typedef unsigned long long u64;

// ---------------- scratch (device globals) ---------------------------------
__device__ __align__(16) float g_bufA[MAX_NODES * D];
__device__ __align__(16) float g_bufB[MAX_NODES * D];
__device__ __align__(16) float g_inv_out[MAX_NODES];
__device__ __align__(16) float g_inv_in[MAX_NODES];
__device__ __align__(16) float g_s1[MAX_NODES];
__device__ __align__(16) int   g_off[MAX_NODES + 16];
__device__ __align__(16) int   g_cur[MAX_NODES];
__device__ __align__(16) int   g_csr[MAX_EDGES];
__device__ __align__(16) int   g_bsum[80];
__device__ __align__(16) int   g_bpre[80];
__device__ __align__(16) float g_T1[LAT * D];             // W2 @ Wc (padded)
__device__ __align__(16) float g_Wfin[LAT * D];           // W1 @ T1 (padded)
__device__ __align__(16) float g_Wall[KMAX * D];          // W_ext @ Wfin
__device__ __align__(16) float g_bfold[64];               // b_ext @ Wfin
__device__ __align__(16) float g_v1[64];                  // b1 @ T1
__device__ __align__(16) float g_c0[64];                  // b2 @ Wc + bc

// packed zero region: out_deg(f32) | deg_in(i32) | poolX[256*56] | poolD | cnt
#define ZR_OUTDEG 0
#define ZR_DEGIN  50000
#define ZR_POOLX  100000
#define ZR_POOLD  114336
#define ZR_CNT    114592
#define ZR_TOTAL  114848
__device__ __align__(16) float g_zregion[ZR_TOTAL];

// ---------------- f32x2 packed math helpers --------------------------------
__device__ __forceinline__ void ffma2(u64& d, u64 a, u64 b) {
    asm("fma.rn.f32x2 %0, %1, %2, %0;" : "+l"(d) : "l"(a), "l"(b));
}
__device__ __forceinline__ float2 unpack2(u64 v) {
    float2 f; asm("mov.b64 {%0, %1}, %2;" : "=f"(f.x), "=f"(f.y) : "l"(v)); return f;
}
__device__ __forceinline__ u64 swap2(u64 v) {
    float2 f = unpack2(v);
    u64 r; asm("mov.b64 %0, {%1, %2};" : "=l"(r) : "f"(f.y), "f"(f.x));
    return r;
}

// ---------------- cp.async helpers -----------------------------------------
__device__ __forceinline__ void cp_async16(uint32_t saddr, const void* gptr) {
    asm volatile("cp.async.ca.shared.global [%0], [%1], 16;"
                 :: "r"(saddr), "l"(gptr));
}
__device__ __forceinline__ void cp_commit() {
    asm volatile("cp.async.commit_group;");
}
__device__ __forceinline__ void cp_wait_all() {
    asm volatile("cp.async.wait_group 0;");
}

// ---------------- L1: prep (zero packed scratch) ----------------------------
__global__ void prep_kernel() {
    int i = blockIdx.x * blockDim.x + threadIdx.x;
    int stride = gridDim.x * blockDim.x;
    float4* z = (float4*)g_zregion;
    float4 zv = make_float4(0.f, 0.f, 0.f, 0.f);
    for (int t = i; t < ZR_TOTAL / 4; t += stride) z[t] = zv;
}

// ---------------- L2: degree histograms || T1 = W2 @ Wc ---------------------
#define WT_BLK 22   // ceil(100*56/256)
__global__ void fuse_deg_wT_kernel(const int* __restrict__ src,
                                   const int* __restrict__ dst, int E,
                                   const float* __restrict__ W2,
                                   const float* __restrict__ Wc) {
    if (blockIdx.x < WT_BLK) {
        int idx = blockIdx.x * 256 + threadIdx.x;
        if (idx < LAT * D) {
            int i = idx / D, j = idx - i * D;
            float a0 = 0.f, a1 = 0.f, a2 = 0.f, a3 = 0.f;
            if (j < NCLASS) {
                const float* w2r = W2 + i * H2;
#pragma unroll
                for (int k = 0; k < H2; k += 4) {
                    a0 += w2r[k]     * Wc[k * NCLASS + j];
                    a1 += w2r[k + 1] * Wc[(k + 1) * NCLASS + j];
                    a2 += w2r[k + 2] * Wc[(k + 2) * NCLASS + j];
                    a3 += w2r[k + 3] * Wc[(k + 3) * NCLASS + j];
                }
            }
            g_T1[idx] = (a0 + a1) + (a2 + a3);
        }
    } else {
        int i = (blockIdx.x - WT_BLK) * 256 + threadIdx.x;
        if (i < E) {
            float* out_deg = g_zregion + ZR_OUTDEG;
            int*   deg_in  = (int*)(g_zregion + ZR_DEGIN);
            atomicAdd(&out_deg[src[i]], 1.0f);
            atomicAdd(&deg_in[dst[i]], 1);
        }
    }
}

// ---------------- L3: scanA || Wfin = W1 @ T1 --------------------------------
#define WF_BLK 6    // ceil(100*56/1024)
__global__ void fuse_scanA_wF_kernel(const int* __restrict__ gid, int n,
                                     const float* __restrict__ W1) {
    if (blockIdx.x < WF_BLK) {
        int idx = blockIdx.x * 1024 + threadIdx.x;
        if (idx < LAT * D) {
            int i = idx / D, j = idx - i * D;
            const float* w1r = W1 + i * LAT;
            float a0 = 0.f, a1 = 0.f, a2 = 0.f, a3 = 0.f;
#pragma unroll
            for (int k = 0; k < LAT; k += 4) {
                a0 += w1r[k]     * g_T1[k * D + j];
                a1 += w1r[k + 1] * g_T1[(k + 1) * D + j];
                a2 += w1r[k + 2] * g_T1[(k + 2) * D + j];
                a3 += w1r[k + 3] * g_T1[(k + 3) * D + j];
            }
            g_Wfin[idx] = (a0 + a1) + (a2 + a3);
        }
        return;
    }
    __shared__ int wsum[32];
    const float* out_deg = g_zregion + ZR_OUTDEG;
    const int*   deg_in  = (const int*)(g_zregion + ZR_DEGIN);
    float* cnt = g_zregion + ZR_CNT;
    int bb = blockIdx.x - WF_BLK;
    int tid = threadIdx.x, lane = tid & 31, warp = tid >> 5;
    int i = bb * 1024 + tid;
    int v = 0;
    if (i < n) {
        v = deg_in[i];
        float ii = rsqrtf(fmaxf((float)v, 1.0f));
        float io = rsqrtf(fmaxf(out_deg[i], 1.0f));
        g_inv_in[i]  = ii;
        g_inv_out[i] = io;
        g_s1[i]      = ii * io;
        atomicAdd(&cnt[gid[i]], 1.0f);
    }
    int s = v;
#pragma unroll
    for (int d = 16; d > 0; d >>= 1) s += __shfl_down_sync(0xffffffffu, s, d);
    if (lane == 0) wsum[warp] = s;
    __syncthreads();
    if (warp == 0) {
        int t = (lane < 32) ? wsum[lane] : 0;
#pragma unroll
        for (int d = 16; d > 0; d >>= 1) t += __shfl_down_sync(0xffffffffu, t, d);
        if (lane == 0) g_bsum[bb] = t;
    }
}

// ---------------- L4: scanB || Wall = W_ext @ Wfin || biases -----------------
// Wall blocks stage g_Wfin in shared (full-MLP load) -> no latency chain.
// Bias block uses fully-unrolled multi-accumulator loops (front-batched LDG).
__global__ void fuse_misc_kernel(int nb, int n,
                                 const float* __restrict__ W_ext, int RAW,
                                 const float* __restrict__ b1,
                                 const float* __restrict__ b2,
                                 const float* __restrict__ Wc,
                                 const float* __restrict__ bc,
                                 const float* __restrict__ b_ext,
                                 int nA) {
    __shared__ float sWf[LAT * D];   // 22.4 KB
    int tid = threadIdx.x;
    if (blockIdx.x == 0) {
        // scanB: exclusive scan of block sums
        __shared__ int s[80];
        if (tid < nb) s[tid] = g_bsum[tid];
        __syncthreads();
        if (tid == 0) {
            int run = 0;
            for (int b = 0; b < nb; b++) { int t = s[b]; s[b] = run; run += t; }
            g_off[n] = run;
        }
        __syncthreads();
        if (tid < nb) g_bpre[tid] = s[tid];
        return;
    }
    if (blockIdx.x <= nA) {
        // stage Wfin -> smem: 5600/256 = 22 independent loads per thread
        for (int t = tid; t < LAT * D; t += 256) sWf[t] = g_Wfin[t];
        __syncthreads();
        int idx = (blockIdx.x - 1) * 256 + tid;
        if (idx < RAW * D) {
            int i = idx / D, c = idx - i * D;
            const float* wer = W_ext + i * LAT;
            float a0 = 0.f, a1 = 0.f, a2 = 0.f, a3 = 0.f;
#pragma unroll
            for (int k = 0; k < LAT; k += 4) {
                a0 += wer[k]     * sWf[k * D + c];
                a1 += wer[k + 1] * sWf[(k + 1) * D + c];
                a2 += wer[k + 2] * sWf[(k + 2) * D + c];
                a3 += wer[k + 3] * sWf[(k + 3) * D + c];
            }
            g_Wall[idx] = (a0 + a1) + (a2 + a3);
        }
        return;
    }
    // bias folds: v1 = b1@T1, bfold = b_ext@Wfin, c0 = b2@Wc + bc
    int j = tid;
    if (j < D) {
        float v0 = 0.f, v1a = 0.f, f0 = 0.f, f1 = 0.f;
#pragma unroll
        for (int k = 0; k < LAT; k += 2) {
            v0 += b1[k]       * g_T1[k * D + j];
            v1a += b1[k + 1]  * g_T1[(k + 1) * D + j];
            f0 += b_ext[k]    * g_Wfin[k * D + j];
            f1 += b_ext[k + 1] * g_Wfin[(k + 1) * D + j];
        }
        g_v1[j] = v0 + v1a;
        g_bfold[j] = f0 + f1;
        if (j < NCLASS) {
            float c0a = 0.f, c1 = 0.f, c2 = 0.f, c3 = 0.f;
#pragma unroll
            for (int k = 0; k < H2; k += 4) {
                c0a += b2[k]     * Wc[k * NCLASS + j];
                c1  += b2[k + 1] * Wc[(k + 1) * NCLASS + j];
                c2  += b2[k + 2] * Wc[(k + 2) * NCLASS + j];
                c3  += b2[k + 3] * Wc[(k + 3) * NCLASS + j];
            }
            g_c0[j] = (c0a + c1) + (c2 + c3) + bc[j];
        }
    }
}

// ---------------- L5: scanC --------------------------------------------------
__global__ void scanC_kernel(int n) {
    __shared__ int wsum[32];
    const int* deg_in = (const int*)(g_zregion + ZR_DEGIN);
    int tid = threadIdx.x, lane = tid & 31, warp = tid >> 5;
    int i = blockIdx.x * 1024 + tid;
    int v = (i < n) ? deg_in[i] : 0;
    int s = v;
#pragma unroll
    for (int d = 1; d < 32; d <<= 1) {
        int t = __shfl_up_sync(0xffffffffu, s, d);
        if (lane >= d) s += t;
    }
    if (lane == 31) wsum[warp] = s;
    __syncthreads();
    if (warp == 0) {
        int ws = wsum[lane];
#pragma unroll
        for (int d = 1; d < 32; d <<= 1) {
            int t = __shfl_up_sync(0xffffffffu, ws, d);
            if (lane >= d) ws += t;
        }
        wsum[lane] = ws;
    }
    __syncthreads();
    int wpre = (warp > 0) ? wsum[warp - 1] : 0;
    int excl = s - v + wpre + g_bpre[blockIdx.x];
    if (i < n) { g_off[i] = excl; g_cur[i] = excl; }
}

// ---------------- L6: GEMM0 || CSR scatter -----------------------------------
#define TM 128
#define KC 32
#define SA 132
#define SW 60
#define ABUF (KC * SA)
#define WBUF (KC * SW)
#define GSMEM ((2 * ABUF + 2 * WBUF) * 4)
__global__ void __launch_bounds__(256, 3) fuse_gemm_scatter_kernel(
        const float* __restrict__ A,
        const float* __restrict__ Wn,
        const float* __restrict__ bias,
        const float* __restrict__ sout,
        float* __restrict__ C, int M, int K, int gb,
        const int* __restrict__ src, const int* __restrict__ dst, int E) {
    if (blockIdx.x >= gb) {
        int i = (blockIdx.x - gb) * 256 + threadIdx.x;
        if (i < E) {
            int p = atomicAdd(&g_cur[dst[i]], 1);
            g_csr[p] = src[i];
        }
        return;
    }
    extern __shared__ float sm[];
    float* AsB = sm;
    float* WsB = sm + 2 * ABUF;
    uint32_t wbase = (uint32_t)__cvta_generic_to_shared(WsB);

    int tid = threadIdx.x;
    int m0 = blockIdx.x * TM;
    bool worker = tid < 224;
    int ty = tid / 14;
    int tx = tid - ty * 14;
    int r0 = ty * 8;
    int c0 = tx * 4;

    u64 accd[4][2], accx[4][2];
#pragma unroll
    for (int p = 0; p < 4; p++) {
        accd[p][0] = accd[p][1] = 0ull;
        accx[p][0] = accx[p][1] = 0ull;
    }

    float4 aQ[4];
    int nk = (K + KC - 1) / KC;

    auto loadW = [&](int k0, int buf) {
#pragma unroll
        for (int s = 0; s < 2; s++) {
            int idx = tid + s * 256;
            if (idx < KC * 14) {
                int kk = idx / 14, c4 = idx - kk * 14;
                int gk = k0 + kk;
                uint32_t dstp = wbase + (buf * WBUF + kk * SW + c4 * 4) * 4;
                if (gk < K) {
                    cp_async16(dstp, &Wn[(size_t)gk * D + c4 * 4]);
                } else {
                    float* d = WsB + buf * WBUF + kk * SW + c4 * 4;
                    d[0] = d[1] = d[2] = d[3] = 0.f;
                }
            }
        }
    };
    auto loadA = [&](int k0) {
#pragma unroll
        for (int s = 0; s < 4; s++) {
            int idx = tid + s * 256;
            int row = idx >> 3, q = idx & 7;
            int gr = m0 + row; if (gr >= M) gr = M - 1;
            int gk = k0 + q * 4;
            if (gk + 3 < K) {
                aQ[s] = *(const float4*)&A[(size_t)gr * K + gk];
            } else {
                aQ[s].x = (gk     < K) ? A[(size_t)gr * K + gk]     : 0.f;
                aQ[s].y = (gk + 1 < K) ? A[(size_t)gr * K + gk + 1] : 0.f;
                aQ[s].z = (gk + 2 < K) ? A[(size_t)gr * K + gk + 2] : 0.f;
                aQ[s].w = (gk + 3 < K) ? A[(size_t)gr * K + gk + 3] : 0.f;
            }
        }
    };
    auto storeA = [&](int buf) {
        float* Ab = AsB + buf * ABUF;
#pragma unroll
        for (int s = 0; s < 4; s++) {
            int idx = tid + s * 256;
            int row = idx >> 3, q = idx & 7;
            float* dstp = Ab + (q * 4) * SA + row;
            dstp[0] = aQ[s].x; dstp[SA] = aQ[s].y; dstp[2 * SA] = aQ[s].z; dstp[3 * SA] = aQ[s].w;
        }
    };

    loadW(0, 0);
    cp_commit();
    loadA(0);
    storeA(0);
    cp_wait_all();
    __syncthreads();

    for (int ch = 0; ch < nk; ch++) {
        int buf = ch & 1;
        if (ch + 1 < nk) {
            loadA((ch + 1) * KC);
            loadW((ch + 1) * KC, buf ^ 1);
            cp_commit();
        }
        if (worker) {
            const float* Ab = AsB + buf * ABUF;
            const float* Wb = WsB + buf * WBUF;
#pragma unroll 4
            for (int k = 0; k < KC; k++) {
                ulonglong2 a01 = *(const ulonglong2*)(Ab + k * SA + r0);
                ulonglong2 a23 = *(const ulonglong2*)(Ab + k * SA + r0 + 4);
                ulonglong2 w   = *(const ulonglong2*)(Wb + k * SW + c0);
                u64 wxs = swap2(w.x);
                u64 wys = swap2(w.y);
                ffma2(accd[0][0], a01.x, w.x);  ffma2(accx[0][0], a01.x, wxs);
                ffma2(accd[0][1], a01.x, w.y);  ffma2(accx[0][1], a01.x, wys);
                ffma2(accd[1][0], a01.y, w.x);  ffma2(accx[1][0], a01.y, wxs);
                ffma2(accd[1][1], a01.y, w.y);  ffma2(accx[1][1], a01.y, wys);
                ffma2(accd[2][0], a23.x, w.x);  ffma2(accx[2][0], a23.x, wxs);
                ffma2(accd[2][1], a23.x, w.y);  ffma2(accx[2][1], a23.x, wys);
                ffma2(accd[3][0], a23.y, w.x);  ffma2(accx[3][0], a23.y, wxs);
                ffma2(accd[3][1], a23.y, w.y);  ffma2(accx[3][1], a23.y, wys);
            }
        }
        if (ch + 1 < nk) {
            storeA(buf ^ 1);
            cp_wait_all();
            __syncthreads();
        }
    }

    if (worker) {
        float4 bv = *(const float4*)&bias[c0];
#pragma unroll
        for (int p = 0; p < 4; p++) {
            float2 d0 = unpack2(accd[p][0]);
            float2 x0 = unpack2(accx[p][0]);
            float2 d1 = unpack2(accd[p][1]);
            float2 x1 = unpack2(accx[p][1]);
            int row = m0 + r0 + 2 * p;
            if (row < M) {
                float so = sout[row];
                float4 v = make_float4((d0.x + bv.x) * so, (x0.x + bv.y) * so,
                                       (d1.x + bv.z) * so, (x1.x + bv.w) * so);
                *(float4*)&C[(size_t)row * D + c0] = v;
            }
            if (row + 1 < M) {
                float so = sout[row + 1];
                float4 v = make_float4((x0.y + bv.x) * so, (d0.y + bv.y) * so,
                                       (x1.y + bv.z) * so, (d1.y + bv.w) * so);
                *(float4*)&C[(size_t)(row + 1) * D + c0] = v;
            }
        }
    }
}

// ---------------- L7/L8: CSR propagation (56-dim, half-warp per node) -------
template <bool POOL>
__global__ void prop_csr_kernel(const float4* __restrict__ xs,
                                float4* __restrict__ agg,
                                const float* __restrict__ scale,
                                const int* __restrict__ gid, int n) {
    int node = (blockIdx.x * blockDim.x + threadIdx.x) >> 4;
    int l = threadIdx.x & 15;
    if (node >= n) return;
    int b = g_off[node], e = g_off[node + 1];
    bool act = l < 14;
    bool dt  = (!POOL) && (l == 14);
    float4 a0 = make_float4(0.f, 0.f, 0.f, 0.f);
    float4 a1 = a0, a2 = a0, a3 = a0;
    float sd = 0.f;
    unsigned base = (unsigned)l;
    int k = b;
    for (; k + 4 <= e; k += 4) {
        int s0 = g_csr[k], s1 = g_csr[k + 1], s2 = g_csr[k + 2], s3 = g_csr[k + 3];
        if (act) {
            float4 v0 = xs[(unsigned)s0 * 14u + base];
            float4 v1 = xs[(unsigned)s1 * 14u + base];
            float4 v2 = xs[(unsigned)s2 * 14u + base];
            float4 v3 = xs[(unsigned)s3 * 14u + base];
            a0.x += v0.x; a0.y += v0.y; a0.z += v0.z; a0.w += v0.w;
            a1.x += v1.x; a1.y += v1.y; a1.z += v1.z; a1.w += v1.w;
            a2.x += v2.x; a2.y += v2.y; a2.z += v2.z; a2.w += v2.w;
            a3.x += v3.x; a3.y += v3.y; a3.z += v3.z; a3.w += v3.w;
        } else if (dt) {
            sd += g_inv_out[s0] + g_inv_out[s1] + g_inv_out[s2] + g_inv_out[s3];
        }
    }
    for (; k < e; k++) {
        int s0 = g_csr[k];
        if (act) {
            float4 v0 = xs[(unsigned)s0 * 14u + base];
            a0.x += v0.x; a0.y += v0.y; a0.z += v0.z; a0.w += v0.w;
        } else if (dt) {
            sd += g_inv_out[s0];
        }
    }
    if (act) {
        float sc = scale[node];
        float x = (a0.x + a1.x + a2.x + a3.x) * sc;
        float y = (a0.y + a1.y + a2.y + a3.y) * sc;
        float z = (a0.z + a1.z + a2.z + a3.z) * sc;
        float w = (a0.w + a1.w + a2.w + a3.w) * sc;
        if (!POOL) {
            agg[(unsigned)node * 14u + base] = make_float4(x, y, z, w);
        } else {
            float* poolX = g_zregion + ZR_POOLX;
            float* p = poolX + (unsigned)gid[node] * D + base * 4u;
            asm volatile("red.global.add.v4.f32 [%0], {%1,%2,%3,%4};"
                         :: "l"(p), "f"(x), "f"(y), "f"(z), "f"(w)
                         : "memory");
        }
    } else if (dt) {
        float* poolD = g_zregion + ZR_POOLD;
        atomicAdd(&poolD[gid[node]], sd * g_inv_in[node]);
    }
}

// ---------------- L9: final --------------------------------------------------
__global__ void final_kernel(float* __restrict__ out) {
    const float* poolX = g_zregion + ZR_POOLX;
    const float* poolD = g_zregion + ZR_POOLD;
    const float* cnt   = g_zregion + ZR_CNT;
    int g = blockIdx.x, tid = threadIdx.x;
    if (tid < NCLASS) {
        float invc = 1.0f / fmaxf(cnt[g], 1.0f);
        out[g * NCLASS + tid] = poolX[g * D + tid] * invc
                              + poolD[g] * invc * g_v1[tid]
                              + g_c0[tid];
    }
}

// ---------------- launch ---------------------------------------------------
extern "C" void kernel_launch(void* const* d_in, const int* in_sizes, int n_in,
                              void* d_out, int out_size) {
    const float* fsnet = (const float*)d_in[0];
    const int*   src   = (const int*)d_in[1];
    const int*   dst   = (const int*)d_in[2];
    const int*   gid   = (const int*)d_in[3];
    const float* W_ext = (const float*)d_in[4];
    const float* b_ext = (const float*)d_in[5];
    const float* W1    = (const float*)d_in[6];
    const float* b1    = (const float*)d_in[7];
    const float* W2    = (const float*)d_in[8];
    const float* b2    = (const float*)d_in[9];
    const float* Wc    = (const float*)d_in[10];
    const float* bc    = (const float*)d_in[11];
    float* out = (float*)d_out;

    int n   = in_sizes[3];
    int E   = in_sizes[1];
    int RAW = in_sizes[4] / LAT;

    float *bufA, *bufB, *inv_out, *inv_in, *s1, *wall, *bfold;
    cudaGetSymbolAddress((void**)&bufA,    g_bufA);
    cudaGetSymbolAddress((void**)&bufB,    g_bufB);
    cudaGetSymbolAddress((void**)&inv_out, g_inv_out);
    cudaGetSymbolAddress((void**)&inv_in,  g_inv_in);
    cudaGetSymbolAddress((void**)&s1,      g_s1);
    cudaGetSymbolAddress((void**)&wall,    g_Wall);
    cudaGetSymbolAddress((void**)&bfold,   g_bfold);

    cudaFuncSetAttribute(fuse_gemm_scatter_kernel,
                         cudaFuncAttributeMaxDynamicSharedMemorySize, GSMEM);

    int nb = (n + 1023) / 1024;          // scanA/scanC blocks
    int eb = (E + 255) / 256;            // edge blocks
    int gb = (n + TM - 1) / TM;          // gemm blocks
    int nA = (RAW * D + 255) / 256;      // Wall blocks

    // L1: zero packed scratch
    prep_kernel<<<148, 256>>>();
    // L2: degree histograms || T1 = W2@Wc
    fuse_deg_wT_kernel<<<WT_BLK + eb, 256>>>(src, dst, E, W2, Wc);
    // L3: scanA (rsqrt + counts + block sums) || Wfin = W1@T1
    fuse_scanA_wF_kernel<<<WF_BLK + nb, 1024>>>(gid, n, W1);
    // L4: scanB || Wall = W_ext@Wfin || bias folds
    fuse_misc_kernel<<<1 + nA + 1, 256>>>(nb, n, W_ext, RAW, b1, b2, Wc, bc, b_ext, nA);
    // L5: scanC -> offsets
    scanC_kernel<<<nb, 1024>>>(n);
    // L6: GEMM0 || CSR scatter
    fuse_gemm_scatter_kernel<<<gb + eb, 256, GSMEM>>>(
        fsnet, wall, bfold, inv_out, bufA, n, RAW, gb, src, dst, E);
    // L7: prop1 (+ fused dtilde): bufB = P(z0) * s1
    int pblocks = (n * 16 + 255) / 256;
    prop_csr_kernel<false><<<pblocks, 256>>>((const float4*)bufA, (float4*)bufB, s1, gid, n);
    // L8: prop2 fused with graph pooling
    prop_csr_kernel<true><<<pblocks, 256>>>((const float4*)bufB, nullptr, inv_in, gid, n);
    // L9: out = poolX/cnt + (poolD/cnt)*v1 + c0
    final_kernel<<<NGRAPH, 64>>>(out);
}

// round 13
// speedup vs baseline: 1.8225x; 1.0751x over previous
#include <cuda_runtime.h>
#include <cstdint>

#define MAX_NODES 50000
#define LAT       100
#define NGRAPH    256
#define H2        200
#define NCLASS    55
#define D         56          // padded class dim (14 float4)
#define MAX_EDGES 800000
#define KMAX      512

typedef unsigned long long u64;

// ---------------- scratch (device globals) ---------------------------------
__device__ __align__(16) float g_bufA[MAX_NODES * D];
__device__ __align__(16) float g_bufB[MAX_NODES * D];
__device__ __align__(16) float g_inv_out[MAX_NODES];
__device__ __align__(16) float g_inv_in[MAX_NODES];
__device__ __align__(16) float g_s1[MAX_NODES];
__device__ __align__(16) int   g_off[MAX_NODES + 16];
__device__ __align__(16) int   g_cur[MAX_NODES];
__device__ __align__(16) int   g_csr[MAX_EDGES];
__device__ __align__(16) u64   g_state[64];               // decoupled-lookback states
__device__            int      g_wfdone;                  // Wfin-done counter
__device__ __align__(16) float g_T1[LAT * D];             // W2 @ Wc (padded)
__device__ __align__(16) float g_Wfin[LAT * D];           // W1 @ T1 (padded)
__device__ __align__(16) float g_Wall[KMAX * D];          // W_ext @ Wfin
__device__ __align__(16) float g_bfold[64];               // b_ext @ Wfin
__device__ __align__(16) float g_v1[64];                  // b1 @ T1
__device__ __align__(16) float g_c0[64];                  // b2 @ Wc + bc

// packed zero region: out_deg(f32) | deg_in(i32) | poolX[256*56] | poolD | cnt
#define ZR_OUTDEG 0
#define ZR_DEGIN  50000
#define ZR_POOLX  100000
#define ZR_POOLD  114336
#define ZR_CNT    114592
#define ZR_TOTAL  114848
__device__ __align__(16) float g_zregion[ZR_TOTAL];

// ---------------- f32x2 packed math helpers --------------------------------
__device__ __forceinline__ void ffma2(u64& d, u64 a, u64 b) {
    asm("fma.rn.f32x2 %0, %1, %2, %0;" : "+l"(d) : "l"(a), "l"(b));
}
__device__ __forceinline__ float2 unpack2(u64 v) {
    float2 f; asm("mov.b64 {%0, %1}, %2;" : "=f"(f.x), "=f"(f.y) : "l"(v)); return f;
}
__device__ __forceinline__ u64 swap2(u64 v) {
    float2 f = unpack2(v);
    u64 r; asm("mov.b64 %0, {%1, %2};" : "=l"(r) : "f"(f.y), "f"(f.x));
    return r;
}

// ---------------- cp.async helpers -----------------------------------------
__device__ __forceinline__ void cp_async16(uint32_t saddr, const void* gptr) {
    asm volatile("cp.async.ca.shared.global [%0], [%1], 16;"
                 :: "r"(saddr), "l"(gptr));
}
__device__ __forceinline__ void cp_commit() {
    asm volatile("cp.async.commit_group;");
}
__device__ __forceinline__ void cp_wait_all() {
    asm volatile("cp.async.wait_group 0;");
}

// ---------------- L1: prep (zero packed scratch + sync state) ---------------
__global__ void prep_kernel() {
    int i = blockIdx.x * blockDim.x + threadIdx.x;
    int stride = gridDim.x * blockDim.x;
    float4* z = (float4*)g_zregion;
    float4 zv = make_float4(0.f, 0.f, 0.f, 0.f);
    for (int t = i; t < ZR_TOTAL / 4; t += stride) z[t] = zv;
    if (i < 64) g_state[i] = 0ull;
    if (i == 64) g_wfdone = 0;
}

// ---------------- L2: degree histograms || T1 = W2 @ Wc ---------------------
#define WT_BLK 22   // ceil(100*56/256)
__global__ void fuse_deg_wT_kernel(const int* __restrict__ src,
                                   const int* __restrict__ dst, int E,
                                   const float* __restrict__ W2,
                                   const float* __restrict__ Wc) {
    if (blockIdx.x < WT_BLK) {
        int idx = blockIdx.x * 256 + threadIdx.x;
        if (idx < LAT * D) {
            int i = idx / D, j = idx - i * D;
            float a0 = 0.f, a1 = 0.f, a2 = 0.f, a3 = 0.f;
            if (j < NCLASS) {
                const float* w2r = W2 + i * H2;
#pragma unroll
                for (int k = 0; k < H2; k += 4) {
                    a0 += w2r[k]     * Wc[k * NCLASS + j];
                    a1 += w2r[k + 1] * Wc[(k + 1) * NCLASS + j];
                    a2 += w2r[k + 2] * Wc[(k + 2) * NCLASS + j];
                    a3 += w2r[k + 3] * Wc[(k + 3) * NCLASS + j];
                }
            }
            g_T1[idx] = (a0 + a1) + (a2 + a3);
        }
    } else {
        int i = (blockIdx.x - WT_BLK) * 256 + threadIdx.x;
        if (i < E) {
            float* out_deg = g_zregion + ZR_OUTDEG;
            int*   deg_in  = (int*)(g_zregion + ZR_DEGIN);
            atomicAdd(&out_deg[src[i]], 1.0f);
            atomicAdd(&deg_in[dst[i]], 1);
        }
    }
}

// ---------------- L3: single-pass scan || Wfin || Wall || biases ------------
// grid (1024 threads each):
//   [0, 6)        : Wfin = W1 @ T1          -> bump g_wfdone when done
//   [6, 20)       : Wall = W_ext @ Wfin     (spin on g_wfdone == 6)
//   [20]          : bias folds              (spin on g_wfdone == 6)
//   [21, 21+nb)   : decoupled-lookback scan of deg_in -> off/cur,
//                   plus rsqrt factors + per-graph counts
#define WF_BLK 6
#define WA_BLK 14   // ceil(256*56/1024)
#define SCAN_BASE (WF_BLK + WA_BLK + 1)
__global__ void __launch_bounds__(1024) fuse_scan_fold_kernel(
        const int* __restrict__ gid, int n, int nb,
        const float* __restrict__ W1,
        const float* __restrict__ W_ext, int RAW,
        const float* __restrict__ b1,
        const float* __restrict__ b2,
        const float* __restrict__ Wc,
        const float* __restrict__ bc,
        const float* __restrict__ b_ext) {
    int tid = threadIdx.x;
    int b = blockIdx.x;

    if (b < WF_BLK) {
        // Wfin = W1 @ T1
        int idx = b * 1024 + tid;
        if (idx < LAT * D) {
            int i = idx / D, j = idx - i * D;
            const float* w1r = W1 + i * LAT;
            float a0 = 0.f, a1 = 0.f, a2 = 0.f, a3 = 0.f;
#pragma unroll
            for (int k = 0; k < LAT; k += 4) {
                a0 += w1r[k]     * g_T1[k * D + j];
                a1 += w1r[k + 1] * g_T1[(k + 1) * D + j];
                a2 += w1r[k + 2] * g_T1[(k + 2) * D + j];
                a3 += w1r[k + 3] * g_T1[(k + 3) * D + j];
            }
            g_Wfin[idx] = (a0 + a1) + (a2 + a3);
        }
        __threadfence();
        __syncthreads();
        if (tid == 0) atomicAdd(&g_wfdone, 1);
        return;
    }
    if (b < WF_BLK + WA_BLK + 1) {
        // wait for Wfin
        if (tid == 0) {
            while (atomicAdd(&g_wfdone, 0) < WF_BLK) { }
        }
        __syncthreads();
        if (b < WF_BLK + WA_BLK) {
            // Wall = W_ext @ Wfin (stage Wfin in smem)
            __shared__ float sWf[LAT * D];
            for (int t = tid; t < LAT * D; t += 1024) sWf[t] = g_Wfin[t];
            __syncthreads();
            int idx = (b - WF_BLK) * 1024 + tid;
            if (idx < RAW * D) {
                int i = idx / D, c = idx - i * D;
                const float* wer = W_ext + i * LAT;
                float a0 = 0.f, a1 = 0.f, a2 = 0.f, a3 = 0.f;
#pragma unroll
                for (int k = 0; k < LAT; k += 4) {
                    a0 += wer[k]     * sWf[k * D + c];
                    a1 += wer[k + 1] * sWf[(k + 1) * D + c];
                    a2 += wer[k + 2] * sWf[(k + 2) * D + c];
                    a3 += wer[k + 3] * sWf[(k + 3) * D + c];
                }
                g_Wall[idx] = (a0 + a1) + (a2 + a3);
            }
        } else {
            // bias folds
            int j = tid;
            if (j < D) {
                float v0 = 0.f, v1a = 0.f, f0 = 0.f, f1 = 0.f;
#pragma unroll
                for (int k = 0; k < LAT; k += 2) {
                    v0  += b1[k]        * g_T1[k * D + j];
                    v1a += b1[k + 1]    * g_T1[(k + 1) * D + j];
                    f0  += b_ext[k]     * g_Wfin[k * D + j];
                    f1  += b_ext[k + 1] * g_Wfin[(k + 1) * D + j];
                }
                g_v1[j] = v0 + v1a;
                g_bfold[j] = f0 + f1;
                if (j < NCLASS) {
                    float c0a = 0.f, c1 = 0.f, c2 = 0.f, c3 = 0.f;
#pragma unroll
                    for (int k = 0; k < H2; k += 4) {
                        c0a += b2[k]     * Wc[k * NCLASS + j];
                        c1  += b2[k + 1] * Wc[(k + 1) * NCLASS + j];
                        c2  += b2[k + 2] * Wc[(k + 2) * NCLASS + j];
                        c3  += b2[k + 3] * Wc[(k + 3) * NCLASS + j];
                    }
                    g_c0[j] = (c0a + c1) + (c2 + c3) + bc[j];
                }
            }
        }
        return;
    }

    // ---- scan blocks: decoupled lookback over deg_in ----
    __shared__ int wsum[32];
    __shared__ int s_prefix;
    const float* out_deg = g_zregion + ZR_OUTDEG;
    const int*   deg_in  = (const int*)(g_zregion + ZR_DEGIN);
    float* cnt = g_zregion + ZR_CNT;
    int bb = b - SCAN_BASE;
    int lane = tid & 31, warp = tid >> 5;
    int i = bb * 1024 + tid;
    int v = 0;
    if (i < n) {
        v = deg_in[i];
        float ii = rsqrtf(fmaxf((float)v, 1.0f));
        float io = rsqrtf(fmaxf(out_deg[i], 1.0f));
        g_inv_in[i]  = ii;
        g_inv_out[i] = io;
        g_s1[i]      = ii * io;
        atomicAdd(&cnt[gid[i]], 1.0f);
    }
    // inclusive scan within block
    int s = v;
#pragma unroll
    for (int d = 1; d < 32; d <<= 1) {
        int t = __shfl_up_sync(0xffffffffu, s, d);
        if (lane >= d) s += t;
    }
    if (lane == 31) wsum[warp] = s;
    __syncthreads();
    if (warp == 0) {
        int ws = wsum[lane];
#pragma unroll
        for (int d = 1; d < 32; d <<= 1) {
            int t = __shfl_up_sync(0xffffffffu, ws, d);
            if (lane >= d) ws += t;
        }
        wsum[lane] = ws;
    }
    __syncthreads();
    int wpre = (warp > 0) ? wsum[warp - 1] : 0;
    int total = wsum[31];
    // lookback
    if (tid == 0) {
        int run = 0;
        if (bb == 0) {
            atomicExch(&g_state[0], (2ull << 32) | (unsigned)total);
        } else {
            atomicExch(&g_state[bb], (1ull << 32) | (unsigned)total);
            int j = bb - 1;
            while (j >= 0) {
                u64 st;
                do { st = atomicAdd(&g_state[j], 0ull); } while ((st >> 32) == 0);
                run += (int)(unsigned)st;
                if ((st >> 32) == 2ull) break;
                j--;
            }
            atomicExch(&g_state[bb], (2ull << 32) | (unsigned)(run + total));
        }
        s_prefix = run;
    }
    __syncthreads();
    int excl = s - v + wpre + s_prefix;
    if (i < n) { g_off[i] = excl; g_cur[i] = excl; }
    if (bb == nb - 1 && tid == 0) g_off[n] = s_prefix + total;
}

// ---------------- L4: GEMM0 || CSR scatter -----------------------------------
#define TM 128
#define KC 32
#define SA 132
#define SW 60
#define ABUF (KC * SA)
#define WBUF (KC * SW)
#define GSMEM ((2 * ABUF + 2 * WBUF) * 4)
__global__ void __launch_bounds__(256, 3) fuse_gemm_scatter_kernel(
        const float* __restrict__ A,
        const float* __restrict__ Wn,
        const float* __restrict__ bias,
        const float* __restrict__ sout,
        float* __restrict__ C, int M, int K, int gb,
        const int* __restrict__ src, const int* __restrict__ dst, int E) {
    if (blockIdx.x >= gb) {
        int i = (blockIdx.x - gb) * 256 + threadIdx.x;
        if (i < E) {
            int p = atomicAdd(&g_cur[dst[i]], 1);
            g_csr[p] = src[i];
        }
        return;
    }
    extern __shared__ float sm[];
    float* AsB = sm;
    float* WsB = sm + 2 * ABUF;
    uint32_t wbase = (uint32_t)__cvta_generic_to_shared(WsB);

    int tid = threadIdx.x;
    int m0 = blockIdx.x * TM;
    bool worker = tid < 224;
    int ty = tid / 14;
    int tx = tid - ty * 14;
    int r0 = ty * 8;
    int c0 = tx * 4;

    u64 accd[4][2], accx[4][2];
#pragma unroll
    for (int p = 0; p < 4; p++) {
        accd[p][0] = accd[p][1] = 0ull;
        accx[p][0] = accx[p][1] = 0ull;
    }

    float4 aQ[4];
    int nk = (K + KC - 1) / KC;

    auto loadW = [&](int k0, int buf) {
#pragma unroll
        for (int s = 0; s < 2; s++) {
            int idx = tid + s * 256;
            if (idx < KC * 14) {
                int kk = idx / 14, c4 = idx - kk * 14;
                int gk = k0 + kk;
                uint32_t dstp = wbase + (buf * WBUF + kk * SW + c4 * 4) * 4;
                if (gk < K) {
                    cp_async16(dstp, &Wn[(size_t)gk * D + c4 * 4]);
                } else {
                    float* d = WsB + buf * WBUF + kk * SW + c4 * 4;
                    d[0] = d[1] = d[2] = d[3] = 0.f;
                }
            }
        }
    };
    auto loadA = [&](int k0) {
#pragma unroll
        for (int s = 0; s < 4; s++) {
            int idx = tid + s * 256;
            int row = idx >> 3, q = idx & 7;
            int gr = m0 + row; if (gr >= M) gr = M - 1;
            int gk = k0 + q * 4;
            if (gk + 3 < K) {
                aQ[s] = *(const float4*)&A[(size_t)gr * K + gk];
            } else {
                aQ[s].x = (gk     < K) ? A[(size_t)gr * K + gk]     : 0.f;
                aQ[s].y = (gk + 1 < K) ? A[(size_t)gr * K + gk + 1] : 0.f;
                aQ[s].z = (gk + 2 < K) ? A[(size_t)gr * K + gk + 2] : 0.f;
                aQ[s].w = (gk + 3 < K) ? A[(size_t)gr * K + gk + 3] : 0.f;
            }
        }
    };
    auto storeA = [&](int buf) {
        float* Ab = AsB + buf * ABUF;
#pragma unroll
        for (int s = 0; s < 4; s++) {
            int idx = tid + s * 256;
            int row = idx >> 3, q = idx & 7;
            float* dstp = Ab + (q * 4) * SA + row;
            dstp[0] = aQ[s].x; dstp[SA] = aQ[s].y; dstp[2 * SA] = aQ[s].z; dstp[3 * SA] = aQ[s].w;
        }
    };

    loadW(0, 0);
    cp_commit();
    loadA(0);
    storeA(0);
    cp_wait_all();
    __syncthreads();

    for (int ch = 0; ch < nk; ch++) {
        int buf = ch & 1;
        if (ch + 1 < nk) {
            loadA((ch + 1) * KC);
            loadW((ch + 1) * KC, buf ^ 1);
            cp_commit();
        }
        if (worker) {
            const float* Ab = AsB + buf * ABUF;
            const float* Wb = WsB + buf * WBUF;
#pragma unroll 4
            for (int k = 0; k < KC; k++) {
                ulonglong2 a01 = *(const ulonglong2*)(Ab + k * SA + r0);
                ulonglong2 a23 = *(const ulonglong2*)(Ab + k * SA + r0 + 4);
                ulonglong2 w   = *(const ulonglong2*)(Wb + k * SW + c0);
                u64 wxs = swap2(w.x);
                u64 wys = swap2(w.y);
                ffma2(accd[0][0], a01.x, w.x);  ffma2(accx[0][0], a01.x, wxs);
                ffma2(accd[0][1], a01.x, w.y);  ffma2(accx[0][1], a01.x, wys);
                ffma2(accd[1][0], a01.y, w.x);  ffma2(accx[1][0], a01.y, wxs);
                ffma2(accd[1][1], a01.y, w.y);  ffma2(accx[1][1], a01.y, wys);
                ffma2(accd[2][0], a23.x, w.x);  ffma2(accx[2][0], a23.x, wxs);
                ffma2(accd[2][1], a23.x, w.y);  ffma2(accx[2][1], a23.x, wys);
                ffma2(accd[3][0], a23.y, w.x);  ffma2(accx[3][0], a23.y, wxs);
                ffma2(accd[3][1], a23.y, w.y);  ffma2(accx[3][1], a23.y, wys);
            }
        }
        if (ch + 1 < nk) {
            storeA(buf ^ 1);
            cp_wait_all();
            __syncthreads();
        }
    }

    if (worker) {
        float4 bv = *(const float4*)&bias[c0];
#pragma unroll
        for (int p = 0; p < 4; p++) {
            float2 d0 = unpack2(accd[p][0]);
            float2 x0 = unpack2(accx[p][0]);
            float2 d1 = unpack2(accd[p][1]);
            float2 x1 = unpack2(accx[p][1]);
            int row = m0 + r0 + 2 * p;
            if (row < M) {
                float so = sout[row];
                float4 v = make_float4((d0.x + bv.x) * so, (x0.x + bv.y) * so,
                                       (d1.x + bv.z) * so, (x1.x + bv.w) * so);
                *(float4*)&C[(size_t)row * D + c0] = v;
            }
            if (row + 1 < M) {
                float so = sout[row + 1];
                float4 v = make_float4((x0.y + bv.x) * so, (d0.y + bv.y) * so,
                                       (x1.y + bv.z) * so, (d1.y + bv.w) * so);
                *(float4*)&C[(size_t)(row + 1) * D + c0] = v;
            }
        }
    }
}

// ---------------- L5/L6: CSR propagation (56-dim, half-warp per node) -------
template <bool POOL>
__global__ void prop_csr_kernel(const float4* __restrict__ xs,
                                float4* __restrict__ agg,
                                const float* __restrict__ scale,
                                const int* __restrict__ gid, int n) {
    int node = (blockIdx.x * blockDim.x + threadIdx.x) >> 4;
    int l = threadIdx.x & 15;
    if (node >= n) return;
    int b = g_off[node], e = g_off[node + 1];
    bool act = l < 14;
    bool dt  = (!POOL) && (l == 14);
    float4 a0 = make_float4(0.f, 0.f, 0.f, 0.f);
    float4 a1 = a0, a2 = a0, a3 = a0;
    float sd = 0.f;
    unsigned base = (unsigned)l;
    int k = b;
    for (; k + 4 <= e; k += 4) {
        int s0 = g_csr[k], s1 = g_csr[k + 1], s2 = g_csr[k + 2], s3 = g_csr[k + 3];
        if (act) {
            float4 v0 = xs[(unsigned)s0 * 14u + base];
            float4 v1 = xs[(unsigned)s1 * 14u + base];
            float4 v2 = xs[(unsigned)s2 * 14u + base];
            float4 v3 = xs[(unsigned)s3 * 14u + base];
            a0.x += v0.x; a0.y += v0.y; a0.z += v0.z; a0.w += v0.w;
            a1.x += v1.x; a1.y += v1.y; a1.z += v1.z; a1.w += v1.w;
            a2.x += v2.x; a2.y += v2.y; a2.z += v2.z; a2.w += v2.w;
            a3.x += v3.x; a3.y += v3.y; a3.z += v3.z; a3.w += v3.w;
        } else if (dt) {
            sd += g_inv_out[s0] + g_inv_out[s1] + g_inv_out[s2] + g_inv_out[s3];
        }
    }
    for (; k < e; k++) {
        int s0 = g_csr[k];
        if (act) {
            float4 v0 = xs[(unsigned)s0 * 14u + base];
            a0.x += v0.x; a0.y += v0.y; a0.z += v0.z; a0.w += v0.w;
        } else if (dt) {
            sd += g_inv_out[s0];
        }
    }
    if (act) {
        float sc = scale[node];
        float x = (a0.x + a1.x + a2.x + a3.x) * sc;
        float y = (a0.y + a1.y + a2.y + a3.y) * sc;
        float z = (a0.z + a1.z + a2.z + a3.z) * sc;
        float w = (a0.w + a1.w + a2.w + a3.w) * sc;
        if (!POOL) {
            agg[(unsigned)node * 14u + base] = make_float4(x, y, z, w);
        } else {
            float* poolX = g_zregion + ZR_POOLX;
            float* p = poolX + (unsigned)gid[node] * D + base * 4u;
            asm volatile("red.global.add.v4.f32 [%0], {%1,%2,%3,%4};"
                         :: "l"(p), "f"(x), "f"(y), "f"(z), "f"(w)
                         : "memory");
        }
    } else if (dt) {
        float* poolD = g_zregion + ZR_POOLD;
        atomicAdd(&poolD[gid[node]], sd * g_inv_in[node]);
    }
}

// ---------------- L7: final --------------------------------------------------
__global__ void final_kernel(float* __restrict__ out) {
    const float* poolX = g_zregion + ZR_POOLX;
    const float* poolD = g_zregion + ZR_POOLD;
    const float* cnt   = g_zregion + ZR_CNT;
    int g = blockIdx.x, tid = threadIdx.x;
    if (tid < NCLASS) {
        float invc = 1.0f / fmaxf(cnt[g], 1.0f);
        out[g * NCLASS + tid] = poolX[g * D + tid] * invc
                              + poolD[g] * invc * g_v1[tid]
                              + g_c0[tid];
    }
}

// ---------------- launch ---------------------------------------------------
extern "C" void kernel_launch(void* const* d_in, const int* in_sizes, int n_in,
                              void* d_out, int out_size) {
    const float* fsnet = (const float*)d_in[0];
    const int*   src   = (const int*)d_in[1];
    const int*   dst   = (const int*)d_in[2];
    const int*   gid   = (const int*)d_in[3];
    const float* W_ext = (const float*)d_in[4];
    const float* b_ext = (const float*)d_in[5];
    const float* W1    = (const float*)d_in[6];
    const float* b1    = (const float*)d_in[7];
    const float* W2    = (const float*)d_in[8];
    const float* b2    = (const float*)d_in[9];
    const float* Wc    = (const float*)d_in[10];
    const float* bc    = (const float*)d_in[11];
    float* out = (float*)d_out;

    int n   = in_sizes[3];
    int E   = in_sizes[1];
    int RAW = in_sizes[4] / LAT;

    float *bufA, *bufB, *inv_out, *inv_in, *s1, *wall, *bfold;
    cudaGetSymbolAddress((void**)&bufA,    g_bufA);
    cudaGetSymbolAddress((void**)&bufB,    g_bufB);
    cudaGetSymbolAddress((void**)&inv_out, g_inv_out);
    cudaGetSymbolAddress((void**)&inv_in,  g_inv_in);
    cudaGetSymbolAddress((void**)&s1,      g_s1);
    cudaGetSymbolAddress((void**)&wall,    g_Wall);
    cudaGetSymbolAddress((void**)&bfold,   g_bfold);

    cudaFuncSetAttribute(fuse_gemm_scatter_kernel,
                         cudaFuncAttributeMaxDynamicSharedMemorySize, GSMEM);

    int nb = (n + 1023) / 1024;          // scan blocks
    int eb = (E + 255) / 256;            // edge blocks
    int gb = (n + TM - 1) / TM;          // gemm blocks

    // L1: zero packed scratch + lookback state
    prep_kernel<<<148, 256>>>();
    // L2: degree histograms || T1 = W2@Wc
    fuse_deg_wT_kernel<<<WT_BLK + eb, 256>>>(src, dst, E, W2, Wc);
    // L3: single-pass scan || Wfin || Wall || biases (flag-ordered)
    fuse_scan_fold_kernel<<<SCAN_BASE + nb, 1024>>>(
        gid, n, nb, W1, W_ext, RAW, b1, b2, Wc, bc, b_ext);
    // L4: GEMM0 || CSR scatter
    fuse_gemm_scatter_kernel<<<gb + eb, 256, GSMEM>>>(
        fsnet, wall, bfold, inv_out, bufA, n, RAW, gb, src, dst, E);
    // L5: prop1 (+ fused dtilde): bufB = P(z0) * s1
    int pblocks = (n * 16 + 255) / 256;
    prop_csr_kernel<false><<<pblocks, 256>>>((const float4*)bufA, (float4*)bufB, s1, gid, n);
    // L6: prop2 fused with graph pooling
    prop_csr_kernel<true><<<pblocks, 256>>>((const float4*)bufB, nullptr, inv_in, gid, n);
    // L7: out = poolX/cnt + (poolD/cnt)*v1 + c0
    final_kernel<<<NGRAPH, 64>>>(out);
}